// round 9
// baseline (speedup 1.0000x reference)
#include <cuda_runtime.h>
#include <cuda_fp16.h>
#include <stdint.h>
#include <math.h>

#define SB 2
#define SS 2048
#define DD 1024
#define BSR 4096
#define NEGV (-1e10f)
#define EPSV 1e-5f

// ---------------------------------------------------------------------------
// Scratch carve-out (one big device global; no allocation allowed)
// ---------------------------------------------------------------------------
__device__ __align__(256) unsigned char g_scratch[209715200ULL];  // 200 MB

#define O_QH   16777216ULL     // q hi fp16         [4096,1024]
#define O_QL   25165824ULL     // q lo fp16
#define O_XH   50331648ULL     // x split
#define O_XL   58720256ULL
#define O_SC   67108864ULL     // scores fp32       [2][2048][2048]
#define O_PH   100663296ULL    // softmax probs split
#define O_PL   117440512ULL
#define O_HDH  134217728ULL    // head split
#define O_HDL  142606336ULL
#define O_HHF  150994944ULL    // h fp32 (pre-LN)
#define O_HNH  167772160ULL    // h split (post-LN)
#define O_HNL  176160768ULL
#define O_FH   184549376ULL    // swish output split
#define O_FL   192937984ULL
#define O_WT   201326592ULL    // wi^T single fp16  [1024,1024]
#define O_WS   205520896ULL    // Wsum^T single fp16

// ---------------------------------------------------------------------------
// Portable sm_80+ primitives: cp.async, ldmatrix, fp16 mma.sync
// ---------------------------------------------------------------------------
__device__ __forceinline__ uint32_t smem_u32(const void* p) {
    uint32_t a;
    asm("{ .reg .u64 t; cvta.to.shared.u64 t, %1; cvt.u32.u64 %0, t; }"
        : "=r"(a) : "l"(p));
    return a;
}
__device__ __forceinline__ void cp16(uint32_t s, const void* g) {
    asm volatile("cp.async.cg.shared.global [%0], [%1], 16;" :: "r"(s), "l"(g));
}
#define CP_COMMIT() asm volatile("cp.async.commit_group;" ::: "memory")
template <int N> __device__ __forceinline__ void cp_wait() {
    asm volatile("cp.async.wait_group %0;" :: "n"(N) : "memory");
}
__device__ __forceinline__ void ldsm4(uint32_t (&r)[4], uint32_t a) {
    asm volatile("ldmatrix.sync.aligned.m8n8.x4.shared.b16 {%0,%1,%2,%3}, [%4];"
                 : "=r"(r[0]), "=r"(r[1]), "=r"(r[2]), "=r"(r[3]) : "r"(a));
}
__device__ __forceinline__ void ldsm4t(uint32_t (&r)[4], uint32_t a) {
    asm volatile("ldmatrix.sync.aligned.m8n8.x4.trans.shared.b16 {%0,%1,%2,%3}, [%4];"
                 : "=r"(r[0]), "=r"(r[1]), "=r"(r[2]), "=r"(r[3]) : "r"(a));
}
__device__ __forceinline__ void mma16816(float (&c)[4], const uint32_t (&a)[4],
                                         uint32_t b0, uint32_t b1) {
    asm volatile(
        "mma.sync.aligned.m16n8k16.row.col.f32.f16.f16.f32 "
        "{%0,%1,%2,%3}, {%4,%5,%6,%7}, {%8,%9}, {%0,%1,%2,%3};"
        : "+f"(c[0]), "+f"(c[1]), "+f"(c[2]), "+f"(c[3])
        : "r"(a[0]), "r"(a[1]), "r"(a[2]), "r"(a[3]), "r"(b0), "r"(b1));
}

__device__ __forceinline__ void split_h(float v, __half& h, __half& l) {
    h = __float2half(v);
    l = __float2half(v - __half2float(h));
}

// ---------------------------------------------------------------------------
// GEMM: C[M,N] = A[M,K] @ B^T. A pre-split fp16 hi/lo (2 terms), B single fp16.
// B layout: TRB=0 -> B stored [N,K]. TRB=1 -> B stored [K,N] (ldmatrix.trans).
// CTA tile 128x128, 8 warps (2m x 4n of 64x32), K-chunk 64, 2-stage, 2 CTA/SM.
// ---------------------------------------------------------------------------
enum { EP_Q = 0, EP_SC = 1, EP_HEAD = 2, EP_BIAS = 3, EP_SWISH = 4, EP_OUT = 5 };

#define ROWB 144                    // 64 fp16 = 128B + 16B pad (conflict-free)
#define MATB (128 * ROWB)           // 18432 bytes per [128,64] matrix tile
#define BTROW 272                   // trans-B row: 128 fp16 + 8 pad
#define BTMATB (64 * BTROW)         // 17408 bytes per [64,128] trans-B tile
#define OFF_AH 0
#define OFF_AL (MATB)
#define OFF_B  (2 * MATB)
#define GEMM_SMEM 110592            // 2 stages x (2*MATB + MATB)

template <int EPI, int TRB>
__global__ __launch_bounds__(256, 2) void gemm_hh(
    const __half* __restrict__ Agh, const __half* __restrict__ Agl,
    const __half* __restrict__ Bg, const __half* __restrict__ Bgl,
    float* __restrict__ Cf, __half* __restrict__ Ch,
    __half* __restrict__ Cl, const float* __restrict__ E,
    int K, int N, long long sA, long long sB, long long sC, long long sE,
    int causal)
{
    extern __shared__ unsigned char smb[];
    constexpr int BMATB = TRB ? BTMATB : MATB;
    constexpr int STAGEB = 2 * MATB + BMATB;

    const int tid = threadIdx.x;
    const int wid = tid >> 5;
    const int lane = tid & 31;
    const int z = blockIdx.z;

    int bi = blockIdx.y, bj = blockIdx.x;
    if (EPI == EP_SC) {
        int xx = blockIdx.x;
        bi = (int)((sqrtf(8.0f * xx + 1.0f) - 1.0f) * 0.5f);
        while ((bi + 1) * (bi + 2) / 2 <= xx) bi++;
        while (bi * (bi + 1) / 2 > xx) bi--;
        bj = xx - bi * (bi + 1) / 2;
    }
    const int row0 = bi * 128;
    const int col0 = bj * 128;
    const bool diag = (EPI == EP_SC) && (col0 == row0);

    const __half* Ah = Agh + (long long)z * sA;
    const __half* Al = Agl + (long long)z * sA;
    const __half* Bm = Bg + (long long)z * sB;
    const __half* Bl = (EPI == EP_HEAD) ? Bgl + (long long)z * sB : nullptr;

    const int kEnd = (causal == 2) ? min(K, row0 + 128) : K;
    const int nch = kEnd >> 6;

    const uint32_t sbase = smem_u32(smb);

    // ---- loaders ----
    // Non-trans matrices [128 rows, 64 k]: 1024 quads; thread t -> row t>>1,
    // quads (t&1)*4 + u (u=0..3).
    const int ldr = tid >> 1;
    const int ldq = (tid & 1) * 4;
    const size_t aRow = (size_t)(row0 + ldr) * K;
    const size_t bRow = (size_t)(col0 + ldr) * K;     // non-trans only
    const uint32_t sRow = (uint32_t)(ldr * ROWB);

    const int m0 = (wid >> 2) * 64;
    const int n0 = (wid & 3) * 32;
    const bool wskip = diag && (n0 > m0 + 63);

    uint32_t aoff[4];
#pragma unroll
    for (int mt = 0; mt < 4; mt++)
        aoff[mt] = (uint32_t)((m0 + mt * 16 + (lane & 15)) * ROWB +
                              (lane >> 4) * 16);
    uint32_t boff[2];
    if (!TRB) {
#pragma unroll
        for (int p = 0; p < 2; p++)
            boff[p] = (uint32_t)((n0 + p * 16 + ((lane >> 4) << 3) + (lane & 7)) *
                                     ROWB +
                                 ((lane >> 3) & 1) * 16);
    } else {
        const int kr = ((lane >> 3) & 1) * 8 + (lane & 7);
#pragma unroll
        for (int p = 0; p < 2; p++) {
            const int nc = n0 + p * 16 + (lane >> 4) * 8;
            boff[p] = (uint32_t)(kr * BTROW + nc * 2);
        }
    }

    float acc[4][4][4] = {};

#define ISSUE(c, st) { \
    const int kk = (c) * 64; \
    const uint32_t sb = sbase + (st) * STAGEB; \
    _Pragma("unroll") for (int u = 0; u < 4; u++) { \
        const int q = ldq + u; \
        cp16(sb + OFF_AH + sRow + q * 16, Ah + aRow + kk + q * 8); \
        cp16(sb + OFF_AL + sRow + q * 16, Al + aRow + kk + q * 8); \
        if (!TRB) { \
            cp16(sb + OFF_B + sRow + q * 16, Bm + bRow + kk + q * 8); \
        } else { \
            const int qi = tid * 4 + u; \
            const int brr = qi >> 4, bqc = qi & 15; \
            const size_t g = (size_t)(kk + brr) * N + col0 + bqc * 8; \
            cp16(sb + OFF_B + (uint32_t)(brr * BTROW + bqc * 16), Bm + g); \
        } \
    } }

    ISSUE(0, 0);
    CP_COMMIT();

    for (int c = 0; c < nch; c++) {
        cp_wait<0>();
        __syncthreads();
        if (c + 1 < nch) { ISSUE(c + 1, (c + 1) & 1); }
        CP_COMMIT();

        const uint32_t stb = sbase + (c & 1) * STAGEB;
        if (!wskip) {
#pragma unroll
            for (int ks = 0; ks < 4; ks++) {
                const uint32_t ksoA = (uint32_t)(ks * 32);
                const uint32_t ksoB = TRB ? (uint32_t)(ks * 16 * BTROW)
                                          : (uint32_t)(ks * 32);
                uint32_t ahf[4][4], alf[4][4], bf[2][4];
#pragma unroll
                for (int mt = 0; mt < 4; mt++) {
                    ldsm4(ahf[mt], stb + OFF_AH + aoff[mt] + ksoA);
                    ldsm4(alf[mt], stb + OFF_AL + aoff[mt] + ksoA);
                }
#pragma unroll
                for (int p = 0; p < 2; p++) {
                    if (!TRB) ldsm4(bf[p], stb + OFF_B + boff[p] + ksoB);
                    else      ldsm4t(bf[p], stb + OFF_B + boff[p] + ksoB);
                }
#pragma unroll
                for (int mt = 0; mt < 4; mt++)
#pragma unroll
                    for (int nt = 0; nt < 4; nt++) {
                        const int p = nt >> 1, h = (nt & 1) * 2;
                        mma16816(acc[mt][nt], ahf[mt], bf[p][h], bf[p][h + 1]);
                    }
#pragma unroll
                for (int mt = 0; mt < 4; mt++)
#pragma unroll
                    for (int nt = 0; nt < 4; nt++) {
                        const int p = nt >> 1, h = (nt & 1) * 2;
                        mma16816(acc[mt][nt], alf[mt], bf[p][h], bf[p][h + 1]);
                    }
            }
        }
        __syncthreads();
    }
#undef ISSUE

    // ------------------- epilogue -------------------
    float* Cfz = (EPI == EP_SC || EPI == EP_BIAS || EPI == EP_OUT)
                     ? Cf + (long long)z * sC : nullptr;
    __half* Chz = (EPI == EP_Q || EPI == EP_HEAD || EPI == EP_SWISH)
                      ? Ch + (long long)z * sC : nullptr;
    __half* Clz = (EPI == EP_Q || EPI == EP_HEAD || EPI == EP_SWISH)
                      ? Cl + (long long)z * sC : nullptr;

#pragma unroll
    for (int mt = 0; mt < 4; mt++) {
#pragma unroll
        for (int nt = 0; nt < 4; nt++) {
#pragma unroll
            for (int half = 0; half < 2; half++) {
                const int r = row0 + m0 + mt * 16 + (lane >> 2) + half * 8;
                const int cc = col0 + n0 + nt * 8 + (lane & 3) * 2;
                float v0 = acc[mt][nt][half * 2];
                float v1 = acc[mt][nt][half * 2 + 1];

                if (EPI == EP_SC) {
                    if (!diag || cc <= r) {
                        v0 *= 0.03125f; v1 *= 0.03125f;
                        *reinterpret_cast<float2*>(&Cfz[(long long)r * N + cc]) =
                            make_float2(v0, v1);
                    }
                } else if (EPI == EP_BIAS) {
                    float2 bb = *reinterpret_cast<const float2*>(&E[cc]);
                    *reinterpret_cast<float2*>(&Cfz[(long long)r * N + cc]) =
                        make_float2(v0 + bb.x, v1 + bb.y);
                } else if (EPI == EP_OUT) {
                    *reinterpret_cast<float2*>(&Cfz[(long long)r * N + cc]) =
                        make_float2(v0, v1);
                } else {
                    if (EPI == EP_HEAD) {
                        // residual q = qh + ql (B operand IS q in [K=S, N=D])
                        __half2 eh = *reinterpret_cast<const __half2*>(
                            &Bm[(long long)r * N + cc]);
                        __half2 el = *reinterpret_cast<const __half2*>(
                            &Bl[(long long)r * N + cc]);
                        v0 += __half2float(eh.x) + __half2float(el.x);
                        v1 += __half2float(eh.y) + __half2float(el.y);
                    }
                    if (EPI == EP_SWISH) {
                        v0 = v0 / (1.0f + expf(-v0));
                        v1 = v1 / (1.0f + expf(-v1));
                    }
                    __half h0, h1, l0, l1;
                    split_h(v0, h0, l0);
                    split_h(v1, h1, l1);
                    *reinterpret_cast<__half2*>(&Chz[(long long)r * N + cc]) =
                        __halves2half2(h0, h1);
                    *reinterpret_cast<__half2*>(&Clz[(long long)r * N + cc]) =
                        __halves2half2(l0, l1);
                }
            }
        }
    }
}

// ---------------------------------------------------------------------------
// Transpose to single fp16: dst[c][r] = fp16(src[r][c]); optional head sum
// ---------------------------------------------------------------------------
template <bool SUMH>
__global__ void tsingle(const float* __restrict__ S, __half* __restrict__ D,
                        int R, int C)
{
    __shared__ float t[32][33];
    const int tx = threadIdx.x, ty = threadIdx.y;
    const int c0 = blockIdx.x * 32, r0 = blockIdx.y * 32;
#pragma unroll
    for (int i = 0; i < 4; i++) {
        int r = r0 + ty + i * 8;
        float v;
        if (SUMH) {
            v = 0.f;
#pragma unroll
            for (int h = 0; h < 8; h++)
                v += S[(size_t)(h * 1024 + r) * C + c0 + tx];
        } else {
            v = S[(size_t)r * C + c0 + tx];
        }
        t[ty + i * 8][tx] = v;
    }
    __syncthreads();
#pragma unroll
    for (int i = 0; i < 4; i++) {
        int orow = c0 + ty + i * 8;
        D[(size_t)orow * R + r0 + tx] = __float2half(t[tx][ty + i * 8]);
    }
}

// ---------------------------------------------------------------------------
// Elementwise 2-term split (fp16)
// ---------------------------------------------------------------------------
__global__ void split_ew(const float* __restrict__ X, __half* __restrict__ H,
                         __half* __restrict__ L)
{
    size_t i = ((size_t)blockIdx.x * 256 + threadIdx.x);
    float4 v = reinterpret_cast<const float4*>(X)[i];
    __half h0, h1, h2, h3, l0, l1, l2, l3;
    split_h(v.x, h0, l0); split_h(v.y, h1, l1);
    split_h(v.z, h2, l2); split_h(v.w, h3, l3);
    reinterpret_cast<__half2*>(H)[i * 2]     = __halves2half2(h0, h1);
    reinterpret_cast<__half2*>(H)[i * 2 + 1] = __halves2half2(h2, h3);
    reinterpret_cast<__half2*>(L)[i * 2]     = __halves2half2(l0, l1);
    reinterpret_cast<__half2*>(L)[i * 2 + 1] = __halves2half2(l2, l3);
}

// ---------------------------------------------------------------------------
// Reductions
// ---------------------------------------------------------------------------
__device__ __forceinline__ float warpMax(float v) {
#pragma unroll
    for (int o = 16; o; o >>= 1) v = fmaxf(v, __shfl_xor_sync(0xffffffffu, v, o));
    return v;
}
__device__ __forceinline__ float warpSum(float v) {
#pragma unroll
    for (int o = 16; o; o >>= 1) v += __shfl_xor_sync(0xffffffffu, v, o);
    return v;
}

// Causal softmax; writes split probs only for cols < ceil((r+1)/128)*128.
__global__ __launch_bounds__(256) void softmax_split(
    const float* __restrict__ Sc, __half* __restrict__ Ph,
    __half* __restrict__ Pl)
{
    const int r = blockIdx.x & (SS - 1);
    const int kLim = ((r >> 7) + 1) << 7;
    const float* row = Sc + (long long)blockIdx.x * SS;
    __half* oh = Ph + (long long)blockIdx.x * SS;
    __half* ol = Pl + (long long)blockIdx.x * SS;
    const int tid = threadIdx.x, lane = tid & 31, w = tid >> 5;
    __shared__ float red[32];

    const int c0 = tid * 4;
    const int c1 = 1024 + tid * 4;
    float4 v0 = make_float4(NEGV, NEGV, NEGV, NEGV);
    float4 v1 = make_float4(NEGV, NEGV, NEGV, NEGV);
    if (c0 < kLim) v0 = reinterpret_cast<const float4*>(row)[tid];
    if (c1 < kLim) v1 = reinterpret_cast<const float4*>(row)[tid + 256];

    float m = -3.4e38f;
    if (c0 + 0 <= r) m = fmaxf(m, v0.x);
    if (c0 + 1 <= r) m = fmaxf(m, v0.y);
    if (c0 + 2 <= r) m = fmaxf(m, v0.z);
    if (c0 + 3 <= r) m = fmaxf(m, v0.w);
    if (c1 + 0 <= r) m = fmaxf(m, v1.x);
    if (c1 + 1 <= r) m = fmaxf(m, v1.y);
    if (c1 + 2 <= r) m = fmaxf(m, v1.z);
    if (c1 + 3 <= r) m = fmaxf(m, v1.w);
    m = warpMax(m);
    if (lane == 0) red[w] = m;
    __syncthreads();
    if (tid < 32) { float x = (tid < 8) ? red[tid] : -3.4e38f; x = warpMax(x);
                    if (tid == 0) red[0] = x; }
    __syncthreads();
    m = red[0];
    __syncthreads();

    float e[8];
    e[0] = (c0 + 0 <= r) ? expf(v0.x - m) : 0.f;
    e[1] = (c0 + 1 <= r) ? expf(v0.y - m) : 0.f;
    e[2] = (c0 + 2 <= r) ? expf(v0.z - m) : 0.f;
    e[3] = (c0 + 3 <= r) ? expf(v0.w - m) : 0.f;
    e[4] = (c1 + 0 <= r) ? expf(v1.x - m) : 0.f;
    e[5] = (c1 + 1 <= r) ? expf(v1.y - m) : 0.f;
    e[6] = (c1 + 2 <= r) ? expf(v1.z - m) : 0.f;
    e[7] = (c1 + 3 <= r) ? expf(v1.w - m) : 0.f;
    float s = e[0] + e[1] + e[2] + e[3] + e[4] + e[5] + e[6] + e[7];
    s = warpSum(s);
    if (lane == 0) red[w] = s;
    __syncthreads();
    if (tid < 32) { float x = (tid < 8) ? red[tid] : 0.f; x = warpSum(x);
                    if (tid == 0) red[0] = x; }
    __syncthreads();
    const float inv = 1.0f / red[0];

    __half h[8], l[8];
#pragma unroll
    for (int u = 0; u < 8; u++) split_h(e[u] * inv, h[u], l[u]);
    __half2* phh = reinterpret_cast<__half2*>(oh);
    __half2* pll = reinterpret_cast<__half2*>(ol);
    if (c0 < kLim) {
        phh[tid * 2]     = __halves2half2(h[0], h[1]);
        phh[tid * 2 + 1] = __halves2half2(h[2], h[3]);
        pll[tid * 2]     = __halves2half2(l[0], l[1]);
        pll[tid * 2 + 1] = __halves2half2(l[2], l[3]);
    }
    if (c1 < kLim) {
        phh[(tid + 256) * 2]     = __halves2half2(h[4], h[5]);
        phh[(tid + 256) * 2 + 1] = __halves2half2(h[6], h[7]);
        pll[(tid + 256) * 2]     = __halves2half2(l[4], l[5]);
        pll[(tid + 256) * 2 + 1] = __halves2half2(l[6], l[7]);
    }
}

// LayerNorm -> split. One block per row (1024 cols).
__global__ __launch_bounds__(256) void ln_split(
    const float* __restrict__ Hf, __half* __restrict__ Oh,
    __half* __restrict__ Ol)
{
    const float* row = Hf + (long long)blockIdx.x * DD;
    __half* oh = Oh + (long long)blockIdx.x * DD;
    __half* ol = Ol + (long long)blockIdx.x * DD;
    const int tid = threadIdx.x, lane = tid & 31, w = tid >> 5;
    __shared__ float r1[32], r2[32];

    float4 v = reinterpret_cast<const float4*>(row)[tid];
    float s = v.x + v.y + v.z + v.w;
    float s2 = v.x * v.x + v.y * v.y + v.z * v.z + v.w * v.w;
    s = warpSum(s); s2 = warpSum(s2);
    if (lane == 0) { r1[w] = s; r2[w] = s2; }
    __syncthreads();
    if (tid < 32) {
        float a = (tid < 8) ? r1[tid] : 0.f;
        float b = (tid < 8) ? r2[tid] : 0.f;
        a = warpSum(a); b = warpSum(b);
        if (tid == 0) { r1[0] = a; r2[0] = b; }
    }
    __syncthreads();
    const float mean = r1[0] * (1.0f / DD);
    const float msq = r2[0] * (1.0f / DD);
    const float inv = rsqrtf(msq - mean * mean + EPSV);

    float y[4] = {(v.x - mean) * inv, (v.y - mean) * inv,
                  (v.z - mean) * inv, (v.w - mean) * inv};
    __half h[4], l[4];
#pragma unroll
    for (int u = 0; u < 4; u++) split_h(y[u], h[u], l[u]);
    reinterpret_cast<__half2*>(oh)[tid * 2]     = __halves2half2(h[0], h[1]);
    reinterpret_cast<__half2*>(oh)[tid * 2 + 1] = __halves2half2(h[2], h[3]);
    reinterpret_cast<__half2*>(ol)[tid * 2]     = __halves2half2(l[0], l[1]);
    reinterpret_cast<__half2*>(ol)[tid * 2 + 1] = __halves2half2(l[2], l[3]);
}

// ---------------------------------------------------------------------------
// Launch
// ---------------------------------------------------------------------------
extern "C" void kernel_launch(void* const* d_in, const int* in_sizes, int n_in,
                              void* d_out, int out_size)
{
    (void)in_sizes; (void)n_in; (void)out_size;
    const float* x     = (const float*)d_in[0];
    const float* wi    = (const float*)d_in[2];
    const float* okern = (const float*)d_in[3];
    const float* obias = (const float*)d_in[4];
    float* out = (float*)d_out;

    unsigned char* base;
    cudaGetSymbolAddress((void**)&base, g_scratch);
    float* sc  = (float*)(base + O_SC);
    float* hhf = (float*)(base + O_HHF);
    __half* qh  = (__half*)(base + O_QH);
    __half* ql  = (__half*)(base + O_QL);
    __half* xh  = (__half*)(base + O_XH);
    __half* xl  = (__half*)(base + O_XL);
    __half* Pph = (__half*)(base + O_PH);
    __half* Ppl = (__half*)(base + O_PL);
    __half* hdh = (__half*)(base + O_HDH);
    __half* hdl = (__half*)(base + O_HDL);
    __half* hnh = (__half*)(base + O_HNH);
    __half* hnl = (__half*)(base + O_HNL);
    __half* fh  = (__half*)(base + O_FH);
    __half* fl  = (__half*)(base + O_FL);
    __half* wT  = (__half*)(base + O_WT);
    __half* wsT = (__half*)(base + O_WS);

    cudaFuncSetAttribute(gemm_hh<EP_Q, 0>,     cudaFuncAttributeMaxDynamicSharedMemorySize, GEMM_SMEM);
    cudaFuncSetAttribute(gemm_hh<EP_SC, 0>,    cudaFuncAttributeMaxDynamicSharedMemorySize, GEMM_SMEM);
    cudaFuncSetAttribute(gemm_hh<EP_HEAD, 1>,  cudaFuncAttributeMaxDynamicSharedMemorySize, GEMM_SMEM);
    cudaFuncSetAttribute(gemm_hh<EP_BIAS, 0>,  cudaFuncAttributeMaxDynamicSharedMemorySize, GEMM_SMEM);
    cudaFuncSetAttribute(gemm_hh<EP_SWISH, 0>, cudaFuncAttributeMaxDynamicSharedMemorySize, GEMM_SMEM);
    cudaFuncSetAttribute(gemm_hh<EP_OUT, 0>,   cudaFuncAttributeMaxDynamicSharedMemorySize, GEMM_SMEM);

    const long long sSD = (long long)SS * DD;   // 2,097,152
    const long long sSS = (long long)SS * SS;   // 4,194,304
    dim3 tb(32, 8);

    // wi^T single, Wsum^T single, x 2-term split
    tsingle<false><<<dim3(32, 32, 1), tb>>>(wi, wT, DD, DD);
    tsingle<true><<<dim3(32, 32, 1), tb>>>(okern, wsT, DD, DD);
    split_ew<<<(BSR * DD) / 1024, 256>>>(x, xh, xl);

    // q = x @ wi  (2-term split out; residual later reconstructed as qh+ql)
    gemm_hh<EP_Q, 0><<<dim3(8, 32, 1), 256, GEMM_SMEM>>>(
        xh, xl, wT, nullptr, nullptr, qh, ql, nullptr, DD, DD, 0, 0, 0, 0, 0);

    // scores = (q @ q^T)/32, lower triangle only (136 tiles per batch)
    gemm_hh<EP_SC, 0><<<dim3(136, 1, 2), 256, GEMM_SMEM>>>(
        qh, ql, qh, nullptr, sc, nullptr, nullptr, nullptr,
        DD, SS, sSD, sSD, sSS, 0, 1);

    // causal softmax -> split probs
    softmax_split<<<SB * SS, 256>>>(sc, Pph, Ppl);

    // head = q + P @ q  (trans-B: q read as [K,N]; residual from qh+ql)
    gemm_hh<EP_HEAD, 1><<<dim3(8, 16, 2), 256, GEMM_SMEM>>>(
        Pph, Ppl, qh, ql, nullptr, hdh, hdl, nullptr,
        SS, DD, sSS, sSD, sSD, sSD, 2);

    // h = head @ Wsum + bias  fp32
    gemm_hh<EP_BIAS, 0><<<dim3(8, 32, 1), 256, GEMM_SMEM>>>(
        hdh, hdl, wsT, nullptr, hhf, nullptr, nullptr, obias,
        DD, DD, 0, 0, 0, 0, 0);

    // layernorm -> split
    ln_split<<<BSR, 256>>>(hhf, hnh, hnl);

    // f = swish(h @ wi)  (split out)
    gemm_hh<EP_SWISH, 0><<<dim3(8, 32, 1), 256, GEMM_SMEM>>>(
        hnh, hnl, wT, nullptr, nullptr, fh, fl, nullptr,
        DD, DD, 0, 0, 0, 0, 0);

    // out = f @ wi  fp32
    gemm_hh<EP_OUT, 0><<<dim3(8, 32, 1), 256, GEMM_SMEM>>>(
        fh, fl, wT, nullptr, out, nullptr, nullptr, nullptr,
        DD, DD, 0, 0, 0, 0, 0);
}

// round 10
// speedup vs baseline: 1.0895x; 1.0895x over previous
#include <cuda_runtime.h>
#include <cuda_fp16.h>
#include <stdint.h>
#include <math.h>

#define SB 2
#define SS 2048
#define DD 1024
#define BSR 4096
#define NEGV (-1e10f)
#define EPSV 1e-5f

// ---------------------------------------------------------------------------
// Scratch carve-out (one big device global; no allocation allowed)
// ---------------------------------------------------------------------------
__device__ __align__(256) unsigned char g_scratch[209715200ULL];  // 200 MB

#define O_QH   16777216ULL     // q hi fp16         [4096,1024]
#define O_QL   25165824ULL     // q lo fp16
#define O_XH   50331648ULL     // x split
#define O_XL   58720256ULL
#define O_SC   67108864ULL     // scores fp32       [2][2048][2048]
#define O_PH   100663296ULL    // softmax probs split
#define O_PL   117440512ULL
#define O_HDH  134217728ULL    // head split
#define O_HDL  142606336ULL
#define O_HHF  150994944ULL    // h fp32 (pre-LN)
#define O_HNH  167772160ULL    // h split (post-LN)
#define O_HNL  176160768ULL
#define O_FH   184549376ULL    // swish output split
#define O_FL   192937984ULL
#define O_WT   201326592ULL    // wi^T single fp16  [1024,1024]
#define O_WS   205520896ULL    // Wsum^T single fp16

// ---------------------------------------------------------------------------
// Portable sm_80+ primitives: cp.async, ldmatrix, fp16 mma.sync
// ---------------------------------------------------------------------------
__device__ __forceinline__ uint32_t smem_u32(const void* p) {
    uint32_t a;
    asm("{ .reg .u64 t; cvta.to.shared.u64 t, %1; cvt.u32.u64 %0, t; }"
        : "=r"(a) : "l"(p));
    return a;
}
__device__ __forceinline__ void cp16(uint32_t s, const void* g) {
    asm volatile("cp.async.cg.shared.global [%0], [%1], 16;" :: "r"(s), "l"(g));
}
#define CP_COMMIT() asm volatile("cp.async.commit_group;" ::: "memory")
template <int N> __device__ __forceinline__ void cp_wait() {
    asm volatile("cp.async.wait_group %0;" :: "n"(N) : "memory");
}
__device__ __forceinline__ void ldsm4(uint32_t (&r)[4], uint32_t a) {
    asm volatile("ldmatrix.sync.aligned.m8n8.x4.shared.b16 {%0,%1,%2,%3}, [%4];"
                 : "=r"(r[0]), "=r"(r[1]), "=r"(r[2]), "=r"(r[3]) : "r"(a));
}
__device__ __forceinline__ void ldsm4t(uint32_t (&r)[4], uint32_t a) {
    asm volatile("ldmatrix.sync.aligned.m8n8.x4.trans.shared.b16 {%0,%1,%2,%3}, [%4];"
                 : "=r"(r[0]), "=r"(r[1]), "=r"(r[2]), "=r"(r[3]) : "r"(a));
}
__device__ __forceinline__ void mma16816(float (&c)[4], const uint32_t (&a)[4],
                                         uint32_t b0, uint32_t b1) {
    asm volatile(
        "mma.sync.aligned.m16n8k16.row.col.f32.f16.f16.f32 "
        "{%0,%1,%2,%3}, {%4,%5,%6,%7}, {%8,%9}, {%0,%1,%2,%3};"
        : "+f"(c[0]), "+f"(c[1]), "+f"(c[2]), "+f"(c[3])
        : "r"(a[0]), "r"(a[1]), "r"(a[2]), "r"(a[3]), "r"(b0), "r"(b1));
}

__device__ __forceinline__ void split_h(float v, __half& h, __half& l) {
    h = __float2half(v);
    l = __float2half(v - __half2float(h));
}

// ---------------------------------------------------------------------------
// GEMM: C[M,N] = A[M,K] @ B^T. A pre-split fp16 hi/lo (2 terms), B single fp16.
// B layout: TRB=0 -> B stored [N,K]. TRB=1 -> B stored [K,N] (ldmatrix.trans).
// CTA tile 128x128, 8 warps (2m x 4n of 64x32), K-chunk 32, THREE-stage
// cp.async pipeline with wait_group<1> (prefetch depth 2), 2 CTA/SM.
// ---------------------------------------------------------------------------
enum { EP_Q = 0, EP_SC = 1, EP_HEAD = 2, EP_BIAS = 3, EP_SWISH = 4, EP_OUT = 5 };

#define RPAD 40
#define MATB (128 * RPAD * 2)       // 10240 bytes: A tiles + non-trans B tile
#define BTROW 272                   // trans-B row bytes: 128 fp16 + 8 pad
#define BTMATB (32 * BTROW)         // 8704 bytes trans-B tile
#define OFF_AH 0
#define OFF_AL (MATB)
#define OFF_B  (2 * MATB)
#define GEMM_SMEM 92160             // 3 stages x 30720 (non-TRB worst case)

template <int EPI, int TRB>
__global__ __launch_bounds__(256, 2) void gemm_hh(
    const __half* __restrict__ Agh, const __half* __restrict__ Agl,
    const __half* __restrict__ Bg, const __half* __restrict__ Bgl,
    float* __restrict__ Cf, __half* __restrict__ Ch,
    __half* __restrict__ Cl, const float* __restrict__ E,
    int K, int N, long long sA, long long sB, long long sC, long long sE,
    int causal)
{
    extern __shared__ unsigned char smb[];
    constexpr int BMATB = TRB ? BTMATB : MATB;
    constexpr int STAGEB = 2 * MATB + BMATB;

    const int tid = threadIdx.x;
    const int wid = tid >> 5;
    const int lane = tid & 31;
    const int z = blockIdx.z;

    int bi = blockIdx.y, bj = blockIdx.x;
    if (EPI == EP_SC) {
        int xx = blockIdx.x;
        bi = (int)((sqrtf(8.0f * xx + 1.0f) - 1.0f) * 0.5f);
        while ((bi + 1) * (bi + 2) / 2 <= xx) bi++;
        while (bi * (bi + 1) / 2 > xx) bi--;
        bj = xx - bi * (bi + 1) / 2;
    }
    const int row0 = bi * 128;
    const int col0 = bj * 128;
    const bool diag = (EPI == EP_SC) && (col0 == row0);

    const __half* Ah = Agh + (long long)z * sA;
    const __half* Al = Agl + (long long)z * sA;
    const __half* Bm = Bg + (long long)z * sB;
    const __half* Bl = (EPI == EP_HEAD) ? Bgl + (long long)z * sB : nullptr;

    const int kEnd = (causal == 2) ? min(K, row0 + 128) : K;
    const int nch = kEnd >> 5;

    const uint32_t sbase = smem_u32(smb);

    const int ldr = tid >> 1;
    const int ldq = (tid & 1) * 2;
    const size_t aRow = (size_t)(row0 + ldr) * K;
    const size_t bRow = (size_t)(col0 + ldr) * K;     // non-trans only
    const uint32_t sRow = (uint32_t)(ldr * (RPAD * 2));

    const int m0 = (wid >> 2) * 64;
    const int n0 = (wid & 3) * 32;
    const bool wskip = diag && (n0 > m0 + 63);

    uint32_t aoff[4];
#pragma unroll
    for (int mt = 0; mt < 4; mt++)
        aoff[mt] = (uint32_t)((m0 + mt * 16 + (lane & 15)) * (RPAD * 2) +
                              ((lane >> 4) * 8) * 2);
    uint32_t boff[2];
    if (!TRB) {
#pragma unroll
        for (int p = 0; p < 2; p++)
            boff[p] = (uint32_t)((n0 + p * 16 + ((lane >> 4) << 3) + (lane & 7)) *
                                     (RPAD * 2) +
                                 (((lane >> 3) & 1) * 8) * 2);
    } else {
        const int kr = ((lane >> 3) & 1) * 8 + (lane & 7);
#pragma unroll
        for (int p = 0; p < 2; p++) {
            const int nc = n0 + p * 16 + (lane >> 4) * 8;
            boff[p] = (uint32_t)(kr * BTROW + nc * 2);
        }
    }

    float acc[4][4][4] = {};

#define ISSUE(c, st) { \
    const int kk = (c) * 32; \
    const uint32_t sb = sbase + (st) * STAGEB; \
    _Pragma("unroll") for (int u = 0; u < 2; u++) { \
        const int q = ldq + u; \
        cp16(sb + OFF_AH + sRow + q * 16, Ah + aRow + kk + q * 8); \
        cp16(sb + OFF_AL + sRow + q * 16, Al + aRow + kk + q * 8); \
        if (!TRB) { \
            cp16(sb + OFF_B + sRow + q * 16, Bm + bRow + kk + q * 8); \
        } else { \
            const int qi = tid * 2 + u; \
            const int brr = qi >> 4, bqc = qi & 15; \
            const size_t g = (size_t)(kk + brr) * N + col0 + bqc * 8; \
            cp16(sb + OFF_B + (uint32_t)(brr * BTROW + bqc * 16), Bm + g); \
        } \
    } }

    // Prologue: 2 chunks in flight (one commit each; empty commit if beyond)
    ISSUE(0, 0);
    CP_COMMIT();
    if (1 < nch) { ISSUE(1, 1); }
    CP_COMMIT();

    int st = 0;                 // stage of chunk c
    for (int c = 0; c < nch; c++) {
        cp_wait<1>();           // chunk c resident; c+1 may still be in flight
        __syncthreads();
        // stage being written = stage of chunk c+2 = stage consumed at c-1
        {
            int st2 = st + 2; if (st2 >= 3) st2 -= 3;
            if (c + 2 < nch) { ISSUE(c + 2, st2); }
        }
        CP_COMMIT();            // exactly one commit per iteration

        const uint32_t stb = sbase + st * STAGEB;
        if (!wskip) {
#pragma unroll
            for (int ks = 0; ks < 2; ks++) {
                const uint32_t ksoA = (uint32_t)(ks * 32);
                const uint32_t ksoB = TRB ? (uint32_t)(ks * 16 * BTROW)
                                          : (uint32_t)(ks * 32);
                uint32_t ahf[4][4], alf[4][4], bf[2][4];
#pragma unroll
                for (int mt = 0; mt < 4; mt++) {
                    ldsm4(ahf[mt], stb + OFF_AH + aoff[mt] + ksoA);
                    ldsm4(alf[mt], stb + OFF_AL + aoff[mt] + ksoA);
                }
#pragma unroll
                for (int p = 0; p < 2; p++) {
                    if (!TRB) ldsm4(bf[p], stb + OFF_B + boff[p] + ksoB);
                    else      ldsm4t(bf[p], stb + OFF_B + boff[p] + ksoB);
                }
#pragma unroll
                for (int mt = 0; mt < 4; mt++)
#pragma unroll
                    for (int nt = 0; nt < 4; nt++) {
                        const int p = nt >> 1, h = (nt & 1) * 2;
                        mma16816(acc[mt][nt], ahf[mt], bf[p][h], bf[p][h + 1]);
                    }
#pragma unroll
                for (int mt = 0; mt < 4; mt++)
#pragma unroll
                    for (int nt = 0; nt < 4; nt++) {
                        const int p = nt >> 1, h = (nt & 1) * 2;
                        mma16816(acc[mt][nt], alf[mt], bf[p][h], bf[p][h + 1]);
                    }
            }
        }
        __syncthreads();
        if (++st >= 3) st = 0;
    }
#undef ISSUE

    // ------------------- epilogue -------------------
    float* Cfz = (EPI == EP_SC || EPI == EP_BIAS || EPI == EP_OUT)
                     ? Cf + (long long)z * sC : nullptr;
    __half* Chz = (EPI == EP_Q || EPI == EP_HEAD || EPI == EP_SWISH)
                      ? Ch + (long long)z * sC : nullptr;
    __half* Clz = (EPI == EP_Q || EPI == EP_HEAD || EPI == EP_SWISH)
                      ? Cl + (long long)z * sC : nullptr;

#pragma unroll
    for (int mt = 0; mt < 4; mt++) {
#pragma unroll
        for (int nt = 0; nt < 4; nt++) {
#pragma unroll
            for (int half = 0; half < 2; half++) {
                const int r = row0 + m0 + mt * 16 + (lane >> 2) + half * 8;
                const int cc = col0 + n0 + nt * 8 + (lane & 3) * 2;
                float v0 = acc[mt][nt][half * 2];
                float v1 = acc[mt][nt][half * 2 + 1];

                if (EPI == EP_SC) {
                    if (!diag || cc <= r) {
                        v0 *= 0.03125f; v1 *= 0.03125f;
                        *reinterpret_cast<float2*>(&Cfz[(long long)r * N + cc]) =
                            make_float2(v0, v1);
                    }
                } else if (EPI == EP_BIAS) {
                    float2 bb = *reinterpret_cast<const float2*>(&E[cc]);
                    *reinterpret_cast<float2*>(&Cfz[(long long)r * N + cc]) =
                        make_float2(v0 + bb.x, v1 + bb.y);
                } else if (EPI == EP_OUT) {
                    *reinterpret_cast<float2*>(&Cfz[(long long)r * N + cc]) =
                        make_float2(v0, v1);
                } else {
                    if (EPI == EP_HEAD) {
                        // residual q = qh + ql (B operand IS q in [K=S, N=D])
                        __half2 eh = *reinterpret_cast<const __half2*>(
                            &Bm[(long long)r * N + cc]);
                        __half2 el = *reinterpret_cast<const __half2*>(
                            &Bl[(long long)r * N + cc]);
                        v0 += __half2float(eh.x) + __half2float(el.x);
                        v1 += __half2float(eh.y) + __half2float(el.y);
                    }
                    if (EPI == EP_SWISH) {
                        v0 = v0 / (1.0f + expf(-v0));
                        v1 = v1 / (1.0f + expf(-v1));
                    }
                    __half h0, h1, l0, l1;
                    split_h(v0, h0, l0);
                    split_h(v1, h1, l1);
                    *reinterpret_cast<__half2*>(&Chz[(long long)r * N + cc]) =
                        __halves2half2(h0, h1);
                    *reinterpret_cast<__half2*>(&Clz[(long long)r * N + cc]) =
                        __halves2half2(l0, l1);
                }
            }
        }
    }
}

// ---------------------------------------------------------------------------
// Transpose to single fp16: dst[c][r] = fp16(src[r][c]); optional head sum
// ---------------------------------------------------------------------------
template <bool SUMH>
__global__ void tsingle(const float* __restrict__ S, __half* __restrict__ D,
                        int R, int C)
{
    __shared__ float t[32][33];
    const int tx = threadIdx.x, ty = threadIdx.y;
    const int c0 = blockIdx.x * 32, r0 = blockIdx.y * 32;
#pragma unroll
    for (int i = 0; i < 4; i++) {
        int r = r0 + ty + i * 8;
        float v;
        if (SUMH) {
            v = 0.f;
#pragma unroll
            for (int h = 0; h < 8; h++)
                v += S[(size_t)(h * 1024 + r) * C + c0 + tx];
        } else {
            v = S[(size_t)r * C + c0 + tx];
        }
        t[ty + i * 8][tx] = v;
    }
    __syncthreads();
#pragma unroll
    for (int i = 0; i < 4; i++) {
        int orow = c0 + ty + i * 8;
        D[(size_t)orow * R + r0 + tx] = __float2half(t[tx][ty + i * 8]);
    }
}

// ---------------------------------------------------------------------------
// Elementwise 2-term split (fp16)
// ---------------------------------------------------------------------------
__global__ void split_ew(const float* __restrict__ X, __half* __restrict__ H,
                         __half* __restrict__ L)
{
    size_t i = ((size_t)blockIdx.x * 256 + threadIdx.x);
    float4 v = reinterpret_cast<const float4*>(X)[i];
    __half h0, h1, h2, h3, l0, l1, l2, l3;
    split_h(v.x, h0, l0); split_h(v.y, h1, l1);
    split_h(v.z, h2, l2); split_h(v.w, h3, l3);
    reinterpret_cast<__half2*>(H)[i * 2]     = __halves2half2(h0, h1);
    reinterpret_cast<__half2*>(H)[i * 2 + 1] = __halves2half2(h2, h3);
    reinterpret_cast<__half2*>(L)[i * 2]     = __halves2half2(l0, l1);
    reinterpret_cast<__half2*>(L)[i * 2 + 1] = __halves2half2(l2, l3);
}

// ---------------------------------------------------------------------------
// Reductions
// ---------------------------------------------------------------------------
__device__ __forceinline__ float warpMax(float v) {
#pragma unroll
    for (int o = 16; o; o >>= 1) v = fmaxf(v, __shfl_xor_sync(0xffffffffu, v, o));
    return v;
}
__device__ __forceinline__ float warpSum(float v) {
#pragma unroll
    for (int o = 16; o; o >>= 1) v += __shfl_xor_sync(0xffffffffu, v, o);
    return v;
}

// Causal softmax; writes split probs only for cols < ceil((r+1)/128)*128.
__global__ __launch_bounds__(256) void softmax_split(
    const float* __restrict__ Sc, __half* __restrict__ Ph,
    __half* __restrict__ Pl)
{
    const int r = blockIdx.x & (SS - 1);
    const int kLim = ((r >> 7) + 1) << 7;
    const float* row = Sc + (long long)blockIdx.x * SS;
    __half* oh = Ph + (long long)blockIdx.x * SS;
    __half* ol = Pl + (long long)blockIdx.x * SS;
    const int tid = threadIdx.x, lane = tid & 31, w = tid >> 5;
    __shared__ float red[32];

    const int c0 = tid * 4;
    const int c1 = 1024 + tid * 4;
    float4 v0 = make_float4(NEGV, NEGV, NEGV, NEGV);
    float4 v1 = make_float4(NEGV, NEGV, NEGV, NEGV);
    if (c0 < kLim) v0 = reinterpret_cast<const float4*>(row)[tid];
    if (c1 < kLim) v1 = reinterpret_cast<const float4*>(row)[tid + 256];

    float m = -3.4e38f;
    if (c0 + 0 <= r) m = fmaxf(m, v0.x);
    if (c0 + 1 <= r) m = fmaxf(m, v0.y);
    if (c0 + 2 <= r) m = fmaxf(m, v0.z);
    if (c0 + 3 <= r) m = fmaxf(m, v0.w);
    if (c1 + 0 <= r) m = fmaxf(m, v1.x);
    if (c1 + 1 <= r) m = fmaxf(m, v1.y);
    if (c1 + 2 <= r) m = fmaxf(m, v1.z);
    if (c1 + 3 <= r) m = fmaxf(m, v1.w);
    m = warpMax(m);
    if (lane == 0) red[w] = m;
    __syncthreads();
    if (tid < 32) { float x = (tid < 8) ? red[tid] : -3.4e38f; x = warpMax(x);
                    if (tid == 0) red[0] = x; }
    __syncthreads();
    m = red[0];
    __syncthreads();

    float e[8];
    e[0] = (c0 + 0 <= r) ? expf(v0.x - m) : 0.f;
    e[1] = (c0 + 1 <= r) ? expf(v0.y - m) : 0.f;
    e[2] = (c0 + 2 <= r) ? expf(v0.z - m) : 0.f;
    e[3] = (c0 + 3 <= r) ? expf(v0.w - m) : 0.f;
    e[4] = (c1 + 0 <= r) ? expf(v1.x - m) : 0.f;
    e[5] = (c1 + 1 <= r) ? expf(v1.y - m) : 0.f;
    e[6] = (c1 + 2 <= r) ? expf(v1.z - m) : 0.f;
    e[7] = (c1 + 3 <= r) ? expf(v1.w - m) : 0.f;
    float s = e[0] + e[1] + e[2] + e[3] + e[4] + e[5] + e[6] + e[7];
    s = warpSum(s);
    if (lane == 0) red[w] = s;
    __syncthreads();
    if (tid < 32) { float x = (tid < 8) ? red[tid] : 0.f; x = warpSum(x);
                    if (tid == 0) red[0] = x; }
    __syncthreads();
    const float inv = 1.0f / red[0];

    __half h[8], l[8];
#pragma unroll
    for (int u = 0; u < 8; u++) split_h(e[u] * inv, h[u], l[u]);
    __half2* phh = reinterpret_cast<__half2*>(oh);
    __half2* pll = reinterpret_cast<__half2*>(ol);
    if (c0 < kLim) {
        phh[tid * 2]     = __halves2half2(h[0], h[1]);
        phh[tid * 2 + 1] = __halves2half2(h[2], h[3]);
        pll[tid * 2]     = __halves2half2(l[0], l[1]);
        pll[tid * 2 + 1] = __halves2half2(l[2], l[3]);
    }
    if (c1 < kLim) {
        phh[(tid + 256) * 2]     = __halves2half2(h[4], h[5]);
        phh[(tid + 256) * 2 + 1] = __halves2half2(h[6], h[7]);
        pll[(tid + 256) * 2]     = __halves2half2(l[4], l[5]);
        pll[(tid + 256) * 2 + 1] = __halves2half2(l[6], l[7]);
    }
}

// LayerNorm -> split. One block per row (1024 cols).
__global__ __launch_bounds__(256) void ln_split(
    const float* __restrict__ Hf, __half* __restrict__ Oh,
    __half* __restrict__ Ol)
{
    const float* row = Hf + (long long)blockIdx.x * DD;
    __half* oh = Oh + (long long)blockIdx.x * DD;
    __half* ol = Ol + (long long)blockIdx.x * DD;
    const int tid = threadIdx.x, lane = tid & 31, w = tid >> 5;
    __shared__ float r1[32], r2[32];

    float4 v = reinterpret_cast<const float4*>(row)[tid];
    float s = v.x + v.y + v.z + v.w;
    float s2 = v.x * v.x + v.y * v.y + v.z * v.z + v.w * v.w;
    s = warpSum(s); s2 = warpSum(s2);
    if (lane == 0) { r1[w] = s; r2[w] = s2; }
    __syncthreads();
    if (tid < 32) {
        float a = (tid < 8) ? r1[tid] : 0.f;
        float b = (tid < 8) ? r2[tid] : 0.f;
        a = warpSum(a); b = warpSum(b);
        if (tid == 0) { r1[0] = a; r2[0] = b; }
    }
    __syncthreads();
    const float mean = r1[0] * (1.0f / DD);
    const float msq = r2[0] * (1.0f / DD);
    const float inv = rsqrtf(msq - mean * mean + EPSV);

    float y[4] = {(v.x - mean) * inv, (v.y - mean) * inv,
                  (v.z - mean) * inv, (v.w - mean) * inv};
    __half h[4], l[4];
#pragma unroll
    for (int u = 0; u < 4; u++) split_h(y[u], h[u], l[u]);
    reinterpret_cast<__half2*>(oh)[tid * 2]     = __halves2half2(h[0], h[1]);
    reinterpret_cast<__half2*>(oh)[tid * 2 + 1] = __halves2half2(h[2], h[3]);
    reinterpret_cast<__half2*>(ol)[tid * 2]     = __halves2half2(l[0], l[1]);
    reinterpret_cast<__half2*>(ol)[tid * 2 + 1] = __halves2half2(l[2], l[3]);
}

// ---------------------------------------------------------------------------
// Launch
// ---------------------------------------------------------------------------
extern "C" void kernel_launch(void* const* d_in, const int* in_sizes, int n_in,
                              void* d_out, int out_size)
{
    (void)in_sizes; (void)n_in; (void)out_size;
    const float* x     = (const float*)d_in[0];
    const float* wi    = (const float*)d_in[2];
    const float* okern = (const float*)d_in[3];
    const float* obias = (const float*)d_in[4];
    float* out = (float*)d_out;

    unsigned char* base;
    cudaGetSymbolAddress((void**)&base, g_scratch);
    float* sc  = (float*)(base + O_SC);
    float* hhf = (float*)(base + O_HHF);
    __half* qh  = (__half*)(base + O_QH);
    __half* ql  = (__half*)(base + O_QL);
    __half* xh  = (__half*)(base + O_XH);
    __half* xl  = (__half*)(base + O_XL);
    __half* Pph = (__half*)(base + O_PH);
    __half* Ppl = (__half*)(base + O_PL);
    __half* hdh = (__half*)(base + O_HDH);
    __half* hdl = (__half*)(base + O_HDL);
    __half* hnh = (__half*)(base + O_HNH);
    __half* hnl = (__half*)(base + O_HNL);
    __half* fh  = (__half*)(base + O_FH);
    __half* fl  = (__half*)(base + O_FL);
    __half* wT  = (__half*)(base + O_WT);
    __half* wsT = (__half*)(base + O_WS);

    cudaFuncSetAttribute(gemm_hh<EP_Q, 0>,     cudaFuncAttributeMaxDynamicSharedMemorySize, GEMM_SMEM);
    cudaFuncSetAttribute(gemm_hh<EP_SC, 0>,    cudaFuncAttributeMaxDynamicSharedMemorySize, GEMM_SMEM);
    cudaFuncSetAttribute(gemm_hh<EP_HEAD, 1>,  cudaFuncAttributeMaxDynamicSharedMemorySize, GEMM_SMEM);
    cudaFuncSetAttribute(gemm_hh<EP_BIAS, 0>,  cudaFuncAttributeMaxDynamicSharedMemorySize, GEMM_SMEM);
    cudaFuncSetAttribute(gemm_hh<EP_SWISH, 0>, cudaFuncAttributeMaxDynamicSharedMemorySize, GEMM_SMEM);
    cudaFuncSetAttribute(gemm_hh<EP_OUT, 0>,   cudaFuncAttributeMaxDynamicSharedMemorySize, GEMM_SMEM);

    const long long sSD = (long long)SS * DD;   // 2,097,152
    const long long sSS = (long long)SS * SS;   // 4,194,304
    dim3 tb(32, 8);

    // wi^T single, Wsum^T single, x 2-term split
    tsingle<false><<<dim3(32, 32, 1), tb>>>(wi, wT, DD, DD);
    tsingle<true><<<dim3(32, 32, 1), tb>>>(okern, wsT, DD, DD);
    split_ew<<<(BSR * DD) / 1024, 256>>>(x, xh, xl);

    // q = x @ wi  (2-term split out; residual later reconstructed as qh+ql)
    gemm_hh<EP_Q, 0><<<dim3(8, 32, 1), 256, GEMM_SMEM>>>(
        xh, xl, wT, nullptr, nullptr, qh, ql, nullptr, DD, DD, 0, 0, 0, 0, 0);

    // scores = (q @ q^T)/32, lower triangle only (136 tiles per batch)
    gemm_hh<EP_SC, 0><<<dim3(136, 1, 2), 256, GEMM_SMEM>>>(
        qh, ql, qh, nullptr, sc, nullptr, nullptr, nullptr,
        DD, SS, sSD, sSD, sSS, 0, 1);

    // causal softmax -> split probs
    softmax_split<<<SB * SS, 256>>>(sc, Pph, Ppl);

    // head = q + P @ q  (trans-B: q read as [K,N]; residual from qh+ql)
    gemm_hh<EP_HEAD, 1><<<dim3(8, 16, 2), 256, GEMM_SMEM>>>(
        Pph, Ppl, qh, ql, nullptr, hdh, hdl, nullptr,
        SS, DD, sSS, sSD, sSD, sSD, 2);

    // h = head @ Wsum + bias  fp32
    gemm_hh<EP_BIAS, 0><<<dim3(8, 32, 1), 256, GEMM_SMEM>>>(
        hdh, hdl, wsT, nullptr, hhf, nullptr, nullptr, obias,
        DD, DD, 0, 0, 0, 0, 0);

    // layernorm -> split
    ln_split<<<BSR, 256>>>(hhf, hnh, hnl);

    // f = swish(h @ wi)  (split out)
    gemm_hh<EP_SWISH, 0><<<dim3(8, 32, 1), 256, GEMM_SMEM>>>(
        hnh, hnl, wT, nullptr, nullptr, fh, fl, nullptr,
        DD, DD, 0, 0, 0, 0, 0);

    // out = f @ wi  fp32
    gemm_hh<EP_OUT, 0><<<dim3(8, 32, 1), 256, GEMM_SMEM>>>(
        fh, fl, wT, nullptr, out, nullptr, nullptr, nullptr,
        DD, DD, 0, 0, 0, 0, 0);
}

// round 13
// speedup vs baseline: 1.2207x; 1.1205x over previous
#include <cuda_runtime.h>
#include <cuda_fp16.h>
#include <stdint.h>
#include <math.h>

#define SB 2
#define SS 2048
#define DD 1024
#define BSR 4096
#define NEGV (-1e10f)
#define EPSV 1e-5f

// ---------------------------------------------------------------------------
// Scratch carve-out (one big device global; no allocation allowed)
// ---------------------------------------------------------------------------
__device__ __align__(256) unsigned char g_scratch[209715200ULL];  // 200 MB

#define O_QH   16777216ULL     // q hi fp16         [4096,1024]
#define O_QL   25165824ULL     // q lo fp16
#define O_XH   50331648ULL     // x split
#define O_XL   58720256ULL
#define O_SC   67108864ULL     // scores fp32       [2][2048][2048]
#define O_PH   100663296ULL    // softmax probs (single fp16)
#define O_HDH  134217728ULL    // head split
#define O_HDL  142606336ULL
#define O_HHF  150994944ULL    // h fp32 (pre-LN)
#define O_HNH  167772160ULL    // h split (post-LN)
#define O_HNL  176160768ULL
#define O_FH   184549376ULL    // swish output split
#define O_FL   192937984ULL
#define O_WT   201326592ULL    // wi^T single fp16  [1024,1024]
#define O_WS   205520896ULL    // Wsum^T single fp16

// ---------------------------------------------------------------------------
// Portable sm_80+ primitives: cp.async, ldmatrix, fp16 mma.sync
// ---------------------------------------------------------------------------
__device__ __forceinline__ uint32_t smem_u32(const void* p) {
    uint32_t a;
    asm("{ .reg .u64 t; cvta.to.shared.u64 t, %1; cvt.u32.u64 %0, t; }"
        : "=r"(a) : "l"(p));
    return a;
}
__device__ __forceinline__ void cp16(uint32_t s, const void* g) {
    asm volatile("cp.async.cg.shared.global [%0], [%1], 16;" :: "r"(s), "l"(g));
}
#define CP_COMMIT() asm volatile("cp.async.commit_group;" ::: "memory")
template <int N> __device__ __forceinline__ void cp_wait() {
    asm volatile("cp.async.wait_group %0;" :: "n"(N) : "memory");
}
__device__ __forceinline__ void ldsm4(uint32_t (&r)[4], uint32_t a) {
    asm volatile("ldmatrix.sync.aligned.m8n8.x4.shared.b16 {%0,%1,%2,%3}, [%4];"
                 : "=r"(r[0]), "=r"(r[1]), "=r"(r[2]), "=r"(r[3]) : "r"(a));
}
__device__ __forceinline__ void ldsm4t(uint32_t (&r)[4], uint32_t a) {
    asm volatile("ldmatrix.sync.aligned.m8n8.x4.trans.shared.b16 {%0,%1,%2,%3}, [%4];"
                 : "=r"(r[0]), "=r"(r[1]), "=r"(r[2]), "=r"(r[3]) : "r"(a));
}
__device__ __forceinline__ void mma16816(float (&c)[4], const uint32_t (&a)[4],
                                         uint32_t b0, uint32_t b1) {
    asm volatile(
        "mma.sync.aligned.m16n8k16.row.col.f32.f16.f16.f32 "
        "{%0,%1,%2,%3}, {%4,%5,%6,%7}, {%8,%9}, {%0,%1,%2,%3};"
        : "+f"(c[0]), "+f"(c[1]), "+f"(c[2]), "+f"(c[3])
        : "r"(a[0]), "r"(a[1]), "r"(a[2]), "r"(a[3]), "r"(b0), "r"(b1));
}

__device__ __forceinline__ void split_h(float v, __half& h, __half& l) {
    h = __float2half(v);
    l = __float2half(v - __half2float(h));
}

// ---------------------------------------------------------------------------
// GEMM: C[M,N] = A[M,K] @ B^T. A fp16 with NA terms (2 = hi/lo split, 1 =
// single), B single fp16. TRB=1 -> B stored [K,N] (ldmatrix.trans).
// CTA tile 128x128, 8 warps (2m x 4n of 64x32), K-chunk 32, 3-stage
// cp.async pipeline with wait_group<1>, 2 CTA/SM.
// ---------------------------------------------------------------------------
enum { EP_Q = 0, EP_SC = 1, EP_HEAD = 2, EP_BIAS = 3, EP_SWISH = 4, EP_OUT = 5 };

#define RPAD 40
#define MATB (128 * RPAD * 2)       // 10240 bytes: A tiles + non-trans B tile
#define BTROW 272                   // trans-B row bytes: 128 fp16 + 8 pad
#define BTMATB (32 * BTROW)         // 8704 bytes trans-B tile
#define OFF_AH 0
#define OFF_AL (MATB)
#define OFF_B  (2 * MATB)
#define GEMM_SMEM 92160             // 3 stages x 30720 (worst case)

template <int EPI, int TRB, int NA>
__global__ __launch_bounds__(256, 2) void gemm_hh(
    const __half* __restrict__ Agh, const __half* __restrict__ Agl,
    const __half* __restrict__ Bg, const __half* __restrict__ Bgl,
    float* __restrict__ Cf, __half* __restrict__ Ch,
    __half* __restrict__ Cl, const float* __restrict__ E,
    int K, int N, long long sA, long long sB, long long sC, long long sE,
    int causal)
{
    extern __shared__ unsigned char smb[];
    constexpr int BMATB = TRB ? BTMATB : MATB;
    constexpr int STAGEB = 2 * MATB + BMATB;

    const int tid = threadIdx.x;
    const int wid = tid >> 5;
    const int lane = tid & 31;
    const int z = blockIdx.z;

    int bi = blockIdx.y, bj = blockIdx.x;
    if (EPI == EP_SC) {
        int xx = blockIdx.x;
        bi = (int)((sqrtf(8.0f * xx + 1.0f) - 1.0f) * 0.5f);
        while ((bi + 1) * (bi + 2) / 2 <= xx) bi++;
        while (bi * (bi + 1) / 2 > xx) bi--;
        bj = xx - bi * (bi + 1) / 2;
    }
    const int row0 = bi * 128;
    const int col0 = bj * 128;
    const bool diag = (EPI == EP_SC) && (col0 == row0);

    const __half* Ah = Agh + (long long)z * sA;
    const __half* Al = (NA == 2) ? Agl + (long long)z * sA : nullptr;
    const __half* Bm = Bg + (long long)z * sB;
    const __half* Bl = (EPI == EP_HEAD) ? Bgl + (long long)z * sB : nullptr;

    const int kEnd = (causal == 2) ? min(K, row0 + 128) : K;
    const int nch = kEnd >> 5;

    const uint32_t sbase = smem_u32(smb);

    const int ldr = tid >> 1;
    const int ldq = (tid & 1) * 2;
    const size_t aRow = (size_t)(row0 + ldr) * K;
    const size_t bRow = (size_t)(col0 + ldr) * K;     // non-trans only
    const uint32_t sRow = (uint32_t)(ldr * (RPAD * 2));

    const int m0 = (wid >> 2) * 64;
    const int n0 = (wid & 3) * 32;
    const bool wskip = diag && (n0 > m0 + 63);

    uint32_t aoff[4];
#pragma unroll
    for (int mt = 0; mt < 4; mt++)
        aoff[mt] = (uint32_t)((m0 + mt * 16 + (lane & 15)) * (RPAD * 2) +
                              ((lane >> 4) * 8) * 2);
    uint32_t boff[2];
    if (!TRB) {
#pragma unroll
        for (int p = 0; p < 2; p++)
            boff[p] = (uint32_t)((n0 + p * 16 + ((lane >> 4) << 3) + (lane & 7)) *
                                     (RPAD * 2) +
                                 (((lane >> 3) & 1) * 8) * 2);
    } else {
        const int kr = ((lane >> 3) & 1) * 8 + (lane & 7);
#pragma unroll
        for (int p = 0; p < 2; p++) {
            const int nc = n0 + p * 16 + (lane >> 4) * 8;
            boff[p] = (uint32_t)(kr * BTROW + nc * 2);
        }
    }

    float acc[4][4][4] = {};

#define ISSUE(c, st) { \
    const int kk = (c) * 32; \
    const uint32_t sb = sbase + (st) * STAGEB; \
    _Pragma("unroll") for (int u = 0; u < 2; u++) { \
        const int q = ldq + u; \
        cp16(sb + OFF_AH + sRow + q * 16, Ah + aRow + kk + q * 8); \
        if (NA == 2) cp16(sb + OFF_AL + sRow + q * 16, Al + aRow + kk + q * 8); \
        if (!TRB) { \
            cp16(sb + OFF_B + sRow + q * 16, Bm + bRow + kk + q * 8); \
        } else { \
            const int qi = tid * 2 + u; \
            const int brr = qi >> 4, bqc = qi & 15; \
            const size_t g = (size_t)(kk + brr) * N + col0 + bqc * 8; \
            cp16(sb + OFF_B + (uint32_t)(brr * BTROW + bqc * 16), Bm + g); \
        } \
    } }

    // Prologue: 2 chunks in flight
    ISSUE(0, 0);
    CP_COMMIT();
    if (1 < nch) { ISSUE(1, 1); }
    CP_COMMIT();

    int st = 0;
    for (int c = 0; c < nch; c++) {
        cp_wait<1>();
        __syncthreads();
        {
            int st2 = st + 2; if (st2 >= 3) st2 -= 3;
            if (c + 2 < nch) { ISSUE(c + 2, st2); }
        }
        CP_COMMIT();

        const uint32_t stb = sbase + st * STAGEB;
        if (!wskip) {
#pragma unroll
            for (int ks = 0; ks < 2; ks++) {
                const uint32_t ksoA = (uint32_t)(ks * 32);
                const uint32_t ksoB = TRB ? (uint32_t)(ks * 16 * BTROW)
                                          : (uint32_t)(ks * 32);
                uint32_t ahf[4][4], alf[4][4], bf[2][4];
#pragma unroll
                for (int mt = 0; mt < 4; mt++) {
                    ldsm4(ahf[mt], stb + OFF_AH + aoff[mt] + ksoA);
                    if (NA == 2)
                        ldsm4(alf[mt], stb + OFF_AL + aoff[mt] + ksoA);
                }
#pragma unroll
                for (int p = 0; p < 2; p++) {
                    if (!TRB) ldsm4(bf[p], stb + OFF_B + boff[p] + ksoB);
                    else      ldsm4t(bf[p], stb + OFF_B + boff[p] + ksoB);
                }
#pragma unroll
                for (int mt = 0; mt < 4; mt++)
#pragma unroll
                    for (int nt = 0; nt < 4; nt++) {
                        const int p = nt >> 1, h = (nt & 1) * 2;
                        mma16816(acc[mt][nt], ahf[mt], bf[p][h], bf[p][h + 1]);
                    }
                if (NA == 2) {
#pragma unroll
                    for (int mt = 0; mt < 4; mt++)
#pragma unroll
                        for (int nt = 0; nt < 4; nt++) {
                            const int p = nt >> 1, h = (nt & 1) * 2;
                            mma16816(acc[mt][nt], alf[mt], bf[p][h], bf[p][h + 1]);
                        }
                }
            }
        }
        __syncthreads();
        if (++st >= 3) st = 0;
    }
#undef ISSUE

    // ------------------- epilogue -------------------
    float* Cfz = (EPI == EP_SC || EPI == EP_BIAS || EPI == EP_OUT)
                     ? Cf + (long long)z * sC : nullptr;
    __half* Chz = (EPI == EP_Q || EPI == EP_HEAD || EPI == EP_SWISH)
                      ? Ch + (long long)z * sC : nullptr;
    __half* Clz = (EPI == EP_Q || EPI == EP_HEAD || EPI == EP_SWISH)
                      ? Cl + (long long)z * sC : nullptr;

#pragma unroll
    for (int mt = 0; mt < 4; mt++) {
#pragma unroll
        for (int nt = 0; nt < 4; nt++) {
#pragma unroll
            for (int half = 0; half < 2; half++) {
                const int r = row0 + m0 + mt * 16 + (lane >> 2) + half * 8;
                const int cc = col0 + n0 + nt * 8 + (lane & 3) * 2;
                float v0 = acc[mt][nt][half * 2];
                float v1 = acc[mt][nt][half * 2 + 1];

                if (EPI == EP_SC) {
                    if (!diag || cc <= r) {
                        v0 *= 0.03125f; v1 *= 0.03125f;
                        *reinterpret_cast<float2*>(&Cfz[(long long)r * N + cc]) =
                            make_float2(v0, v1);
                    }
                } else if (EPI == EP_BIAS) {
                    float2 bb = *reinterpret_cast<const float2*>(&E[cc]);
                    *reinterpret_cast<float2*>(&Cfz[(long long)r * N + cc]) =
                        make_float2(v0 + bb.x, v1 + bb.y);
                } else if (EPI == EP_OUT) {
                    *reinterpret_cast<float2*>(&Cfz[(long long)r * N + cc]) =
                        make_float2(v0, v1);
                } else {
                    if (EPI == EP_HEAD) {
                        // residual q = qh + ql (B operand IS q in [K=S, N=D])
                        __half2 eh = *reinterpret_cast<const __half2*>(
                            &Bm[(long long)r * N + cc]);
                        __half2 el = *reinterpret_cast<const __half2*>(
                            &Bl[(long long)r * N + cc]);
                        v0 += __half2float(eh.x) + __half2float(el.x);
                        v1 += __half2float(eh.y) + __half2float(el.y);
                    }
                    if (EPI == EP_SWISH) {
                        v0 = v0 / (1.0f + expf(-v0));
                        v1 = v1 / (1.0f + expf(-v1));
                    }
                    __half h0, h1, l0, l1;
                    split_h(v0, h0, l0);
                    split_h(v1, h1, l1);
                    *reinterpret_cast<__half2*>(&Chz[(long long)r * N + cc]) =
                        __halves2half2(h0, h1);
                    *reinterpret_cast<__half2*>(&Clz[(long long)r * N + cc]) =
                        __halves2half2(l0, l1);
                }
            }
        }
    }
}

// ---------------------------------------------------------------------------
// Transpose to single fp16: dst[c][r] = fp16(src[r][c]); optional head sum
// ---------------------------------------------------------------------------
template <bool SUMH>
__global__ void tsingle(const float* __restrict__ S, __half* __restrict__ D,
                        int R, int C)
{
    __shared__ float t[32][33];
    const int tx = threadIdx.x, ty = threadIdx.y;
    const int c0 = blockIdx.x * 32, r0 = blockIdx.y * 32;
#pragma unroll
    for (int i = 0; i < 4; i++) {
        int r = r0 + ty + i * 8;
        float v;
        if (SUMH) {
            v = 0.f;
#pragma unroll
            for (int h = 0; h < 8; h++)
                v += S[(size_t)(h * 1024 + r) * C + c0 + tx];
        } else {
            v = S[(size_t)r * C + c0 + tx];
        }
        t[ty + i * 8][tx] = v;
    }
    __syncthreads();
#pragma unroll
    for (int i = 0; i < 4; i++) {
        int orow = c0 + ty + i * 8;
        D[(size_t)orow * R + r0 + tx] = __float2half(t[tx][ty + i * 8]);
    }
}

// ---------------------------------------------------------------------------
// Elementwise 2-term split (fp16)
// ---------------------------------------------------------------------------
__global__ void split_ew(const float* __restrict__ X, __half* __restrict__ H,
                         __half* __restrict__ L)
{
    size_t i = ((size_t)blockIdx.x * 256 + threadIdx.x);
    float4 v = reinterpret_cast<const float4*>(X)[i];
    __half h0, h1, h2, h3, l0, l1, l2, l3;
    split_h(v.x, h0, l0); split_h(v.y, h1, l1);
    split_h(v.z, h2, l2); split_h(v.w, h3, l3);
    reinterpret_cast<__half2*>(H)[i * 2]     = __halves2half2(h0, h1);
    reinterpret_cast<__half2*>(H)[i * 2 + 1] = __halves2half2(h2, h3);
    reinterpret_cast<__half2*>(L)[i * 2]     = __halves2half2(l0, l1);
    reinterpret_cast<__half2*>(L)[i * 2 + 1] = __halves2half2(l2, l3);
}

// ---------------------------------------------------------------------------
// Reductions
// ---------------------------------------------------------------------------
__device__ __forceinline__ float warpMax(float v) {
#pragma unroll
    for (int o = 16; o; o >>= 1) v = fmaxf(v, __shfl_xor_sync(0xffffffffu, v, o));
    return v;
}
__device__ __forceinline__ float warpSum(float v) {
#pragma unroll
    for (int o = 16; o; o >>= 1) v += __shfl_xor_sync(0xffffffffu, v, o);
    return v;
}

// Causal softmax; writes SINGLE fp16 probs only for cols < kLim.
__global__ __launch_bounds__(256) void softmax_single(
    const float* __restrict__ Sc, __half* __restrict__ Ph)
{
    const int r = blockIdx.x & (SS - 1);
    const int kLim = ((r >> 7) + 1) << 7;
    const float* row = Sc + (long long)blockIdx.x * SS;
    __half* oh = Ph + (long long)blockIdx.x * SS;
    const int tid = threadIdx.x, lane = tid & 31, w = tid >> 5;
    __shared__ float red[32];

    const int c0 = tid * 4;
    const int c1 = 1024 + tid * 4;
    float4 v0 = make_float4(NEGV, NEGV, NEGV, NEGV);
    float4 v1 = make_float4(NEGV, NEGV, NEGV, NEGV);
    if (c0 < kLim) v0 = reinterpret_cast<const float4*>(row)[tid];
    if (c1 < kLim) v1 = reinterpret_cast<const float4*>(row)[tid + 256];

    float m = -3.4e38f;
    if (c0 + 0 <= r) m = fmaxf(m, v0.x);
    if (c0 + 1 <= r) m = fmaxf(m, v0.y);
    if (c0 + 2 <= r) m = fmaxf(m, v0.z);
    if (c0 + 3 <= r) m = fmaxf(m, v0.w);
    if (c1 + 0 <= r) m = fmaxf(m, v1.x);
    if (c1 + 1 <= r) m = fmaxf(m, v1.y);
    if (c1 + 2 <= r) m = fmaxf(m, v1.z);
    if (c1 + 3 <= r) m = fmaxf(m, v1.w);
    m = warpMax(m);
    if (lane == 0) red[w] = m;
    __syncthreads();
    if (tid < 32) { float x = (tid < 8) ? red[tid] : -3.4e38f; x = warpMax(x);
                    if (tid == 0) red[0] = x; }
    __syncthreads();
    m = red[0];
    __syncthreads();

    float e[8];
    e[0] = (c0 + 0 <= r) ? expf(v0.x - m) : 0.f;
    e[1] = (c0 + 1 <= r) ? expf(v0.y - m) : 0.f;
    e[2] = (c0 + 2 <= r) ? expf(v0.z - m) : 0.f;
    e[3] = (c0 + 3 <= r) ? expf(v0.w - m) : 0.f;
    e[4] = (c1 + 0 <= r) ? expf(v1.x - m) : 0.f;
    e[5] = (c1 + 1 <= r) ? expf(v1.y - m) : 0.f;
    e[6] = (c1 + 2 <= r) ? expf(v1.z - m) : 0.f;
    e[7] = (c1 + 3 <= r) ? expf(v1.w - m) : 0.f;
    float s = e[0] + e[1] + e[2] + e[3] + e[4] + e[5] + e[6] + e[7];
    s = warpSum(s);
    if (lane == 0) red[w] = s;
    __syncthreads();
    if (tid < 32) { float x = (tid < 8) ? red[tid] : 0.f; x = warpSum(x);
                    if (tid == 0) red[0] = x; }
    __syncthreads();
    const float inv = 1.0f / red[0];

    __half h[8];
#pragma unroll
    for (int u = 0; u < 8; u++) h[u] = __float2half(e[u] * inv);
    __half2* phh = reinterpret_cast<__half2*>(oh);
    if (c0 < kLim) {
        phh[tid * 2]     = __halves2half2(h[0], h[1]);
        phh[tid * 2 + 1] = __halves2half2(h[2], h[3]);
    }
    if (c1 < kLim) {
        phh[(tid + 256) * 2]     = __halves2half2(h[4], h[5]);
        phh[(tid + 256) * 2 + 1] = __halves2half2(h[6], h[7]);
    }
}

// LayerNorm -> split. One block per row (1024 cols).
__global__ __launch_bounds__(256) void ln_split(
    const float* __restrict__ Hf, __half* __restrict__ Oh,
    __half* __restrict__ Ol)
{
    const float* row = Hf + (long long)blockIdx.x * DD;
    __half* oh = Oh + (long long)blockIdx.x * DD;
    __half* ol = Ol + (long long)blockIdx.x * DD;
    const int tid = threadIdx.x, lane = tid & 31, w = tid >> 5;
    __shared__ float r1[32], r2[32];

    float4 v = reinterpret_cast<const float4*>(row)[tid];
    float s = v.x + v.y + v.z + v.w;
    float s2 = v.x * v.x + v.y * v.y + v.z * v.z + v.w * v.w;
    s = warpSum(s); s2 = warpSum(s2);
    if (lane == 0) { r1[w] = s; r2[w] = s2; }
    __syncthreads();
    if (tid < 32) {
        float a = (tid < 8) ? r1[tid] : 0.f;
        float b = (tid < 8) ? r2[tid] : 0.f;
        a = warpSum(a); b = warpSum(b);
        if (tid == 0) { r1[0] = a; r2[0] = b; }
    }
    __syncthreads();
    const float mean = r1[0] * (1.0f / DD);
    const float msq = r2[0] * (1.0f / DD);
    const float inv = rsqrtf(msq - mean * mean + EPSV);

    float y[4] = {(v.x - mean) * inv, (v.y - mean) * inv,
                  (v.z - mean) * inv, (v.w - mean) * inv};
    __half h[4], l[4];
#pragma unroll
    for (int u = 0; u < 4; u++) split_h(y[u], h[u], l[u]);
    reinterpret_cast<__half2*>(oh)[tid * 2]     = __halves2half2(h[0], h[1]);
    reinterpret_cast<__half2*>(oh)[tid * 2 + 1] = __halves2half2(h[2], h[3]);
    reinterpret_cast<__half2*>(ol)[tid * 2]     = __halves2half2(l[0], l[1]);
    reinterpret_cast<__half2*>(ol)[tid * 2 + 1] = __halves2half2(l[2], l[3]);
}

// ---------------------------------------------------------------------------
// Launch
// ---------------------------------------------------------------------------
extern "C" void kernel_launch(void* const* d_in, const int* in_sizes, int n_in,
                              void* d_out, int out_size)
{
    (void)in_sizes; (void)n_in; (void)out_size;
    const float* x     = (const float*)d_in[0];
    const float* wi    = (const float*)d_in[2];
    const float* okern = (const float*)d_in[3];
    const float* obias = (const float*)d_in[4];
    float* out = (float*)d_out;

    unsigned char* base;
    cudaGetSymbolAddress((void**)&base, g_scratch);
    float* sc  = (float*)(base + O_SC);
    float* hhf = (float*)(base + O_HHF);
    __half* qh  = (__half*)(base + O_QH);
    __half* ql  = (__half*)(base + O_QL);
    __half* xh  = (__half*)(base + O_XH);
    __half* xl  = (__half*)(base + O_XL);
    __half* Pph = (__half*)(base + O_PH);
    __half* hdh = (__half*)(base + O_HDH);
    __half* hdl = (__half*)(base + O_HDL);
    __half* hnh = (__half*)(base + O_HNH);
    __half* hnl = (__half*)(base + O_HNL);
    __half* fh  = (__half*)(base + O_FH);
    __half* fl  = (__half*)(base + O_FL);
    __half* wT  = (__half*)(base + O_WT);
    __half* wsT = (__half*)(base + O_WS);

    cudaFuncSetAttribute(gemm_hh<EP_Q, 0, 2>,     cudaFuncAttributeMaxDynamicSharedMemorySize, GEMM_SMEM);
    cudaFuncSetAttribute(gemm_hh<EP_SC, 0, 2>,    cudaFuncAttributeMaxDynamicSharedMemorySize, GEMM_SMEM);
    cudaFuncSetAttribute(gemm_hh<EP_HEAD, 1, 1>,  cudaFuncAttributeMaxDynamicSharedMemorySize, GEMM_SMEM);
    cudaFuncSetAttribute(gemm_hh<EP_BIAS, 0, 2>,  cudaFuncAttributeMaxDynamicSharedMemorySize, GEMM_SMEM);
    cudaFuncSetAttribute(gemm_hh<EP_SWISH, 0, 2>, cudaFuncAttributeMaxDynamicSharedMemorySize, GEMM_SMEM);
    cudaFuncSetAttribute(gemm_hh<EP_OUT, 0, 2>,   cudaFuncAttributeMaxDynamicSharedMemorySize, GEMM_SMEM);

    const long long sSD = (long long)SS * DD;   // 2,097,152
    const long long sSS = (long long)SS * SS;   // 4,194,304
    dim3 tb(32, 8);

    // wi^T single, Wsum^T single, x 2-term split
    tsingle<false><<<dim3(32, 32, 1), tb>>>(wi, wT, DD, DD);
    tsingle<true><<<dim3(32, 32, 1), tb>>>(okern, wsT, DD, DD);
    split_ew<<<(BSR * DD) / 1024, 256>>>(x, xh, xl);

    // q = x @ wi  (2-term split out; residual later reconstructed as qh+ql)
    gemm_hh<EP_Q, 0, 2><<<dim3(8, 32, 1), 256, GEMM_SMEM>>>(
        xh, xl, wT, nullptr, nullptr, qh, ql, nullptr, DD, DD, 0, 0, 0, 0, 0);

    // scores = (q @ q^T)/32, lower triangle only (136 tiles per batch)
    gemm_hh<EP_SC, 0, 2><<<dim3(136, 1, 2), 256, GEMM_SMEM>>>(
        qh, ql, qh, nullptr, sc, nullptr, nullptr, nullptr,
        DD, SS, sSD, sSD, sSS, 0, 1);

    // causal softmax -> single fp16 probs
    softmax_single<<<SB * SS, 256>>>(sc, Pph);

    // head = q + P @ q  (single-A x single-B; trans-B; residual from qh+ql)
    gemm_hh<EP_HEAD, 1, 1><<<dim3(8, 16, 2), 256, GEMM_SMEM>>>(
        Pph, nullptr, qh, ql, nullptr, hdh, hdl, nullptr,
        SS, DD, sSS, sSD, sSD, sSD, 2);

    // h = head @ Wsum + bias  fp32
    gemm_hh<EP_BIAS, 0, 2><<<dim3(8, 32, 1), 256, GEMM_SMEM>>>(
        hdh, hdl, wsT, nullptr, hhf, nullptr, nullptr, obias,
        DD, DD, 0, 0, 0, 0, 0);

    // layernorm -> split
    ln_split<<<BSR, 256>>>(hhf, hnh, hnl);

    // f = swish(h @ wi)  (split out)
    gemm_hh<EP_SWISH, 0, 2><<<dim3(8, 32, 1), 256, GEMM_SMEM>>>(
        hnh, hnl, wT, nullptr, nullptr, fh, fl, nullptr,
        DD, DD, 0, 0, 0, 0, 0);

    // out = f @ wi  fp32
    gemm_hh<EP_OUT, 0, 2><<<dim3(8, 32, 1), 256, GEMM_SMEM>>>(
        fh, fl, wT, nullptr, out, nullptr, nullptr, nullptr,
        DD, DD, 0, 0, 0, 0, 0);
}

// round 15
// speedup vs baseline: 1.4835x; 1.2153x over previous
#include <cuda_runtime.h>
#include <cuda_fp16.h>
#include <stdint.h>
#include <math.h>

#define SB 2
#define SS 2048
#define DD 1024
#define BSR 4096
#define NEGV (-1e10f)
#define EPSV 1e-5f

// ---------------------------------------------------------------------------
// Scratch carve-out (one big device global; no allocation allowed)
// ---------------------------------------------------------------------------
__device__ __align__(256) unsigned char g_scratch[209715200ULL];  // 200 MB

#define O_QH   16777216ULL     // q hi fp16         [4096,1024]
#define O_QL   25165824ULL     // q lo fp16
#define O_XH   50331648ULL     // x split
#define O_XL   58720256ULL
#define O_SC   67108864ULL     // scores fp32       [2][2048][2048]
#define O_PH   100663296ULL    // softmax probs (single fp16)
#define O_HDH  134217728ULL    // head single fp16
#define O_HHF  150994944ULL    // h fp32 (pre-LN)
#define O_HNH  167772160ULL    // h single fp16 (post-LN)
#define O_FH   184549376ULL    // swish output single fp16
#define O_WT   201326592ULL    // wi^T single fp16  [1024,1024]
#define O_WS   205520896ULL    // Wsum^T single fp16

// ---------------------------------------------------------------------------
// Portable sm_80+ primitives: cp.async, ldmatrix, fp16 mma.sync
// ---------------------------------------------------------------------------
__device__ __forceinline__ uint32_t smem_u32(const void* p) {
    uint32_t a;
    asm("{ .reg .u64 t; cvta.to.shared.u64 t, %1; cvt.u32.u64 %0, t; }"
        : "=r"(a) : "l"(p));
    return a;
}
__device__ __forceinline__ void cp16(uint32_t s, const void* g) {
    asm volatile("cp.async.cg.shared.global [%0], [%1], 16;" :: "r"(s), "l"(g));
}
#define CP_COMMIT() asm volatile("cp.async.commit_group;" ::: "memory")
template <int N> __device__ __forceinline__ void cp_wait() {
    asm volatile("cp.async.wait_group %0;" :: "n"(N) : "memory");
}
__device__ __forceinline__ void ldsm4(uint32_t (&r)[4], uint32_t a) {
    asm volatile("ldmatrix.sync.aligned.m8n8.x4.shared.b16 {%0,%1,%2,%3}, [%4];"
                 : "=r"(r[0]), "=r"(r[1]), "=r"(r[2]), "=r"(r[3]) : "r"(a));
}
__device__ __forceinline__ void ldsm4t(uint32_t (&r)[4], uint32_t a) {
    asm volatile("ldmatrix.sync.aligned.m8n8.x4.trans.shared.b16 {%0,%1,%2,%3}, [%4];"
                 : "=r"(r[0]), "=r"(r[1]), "=r"(r[2]), "=r"(r[3]) : "r"(a));
}
__device__ __forceinline__ void mma16816(float (&c)[4], const uint32_t (&a)[4],
                                         uint32_t b0, uint32_t b1) {
    asm volatile(
        "mma.sync.aligned.m16n8k16.row.col.f32.f16.f16.f32 "
        "{%0,%1,%2,%3}, {%4,%5,%6,%7}, {%8,%9}, {%0,%1,%2,%3};"
        : "+f"(c[0]), "+f"(c[1]), "+f"(c[2]), "+f"(c[3])
        : "r"(a[0]), "r"(a[1]), "r"(a[2]), "r"(a[3]), "r"(b0), "r"(b1));
}

__device__ __forceinline__ void split_h(float v, __half& h, __half& l) {
    h = __float2half(v);
    l = __float2half(v - __half2float(h));
}

// ---------------------------------------------------------------------------
// GEMM: C[M,N] = A[M,K] @ B^T. A fp16 with NA terms (2 = hi/lo split, 1 =
// single), B single fp16. TRB=1 -> B stored [K,N] (ldmatrix.trans).
// WS=1 -> epilogue writes only the hi fp16 plane (no low plane).
// CTA tile 128x128, 8 warps (2m x 4n of 64x32), K-chunk 32, 3-stage
// cp.async pipeline with wait_group<1>, 2 CTA/SM.
// ---------------------------------------------------------------------------
enum { EP_Q = 0, EP_SC = 1, EP_HEAD = 2, EP_BIAS = 3, EP_SWISH = 4, EP_OUT = 5 };

#define RPAD 40
#define MATB (128 * RPAD * 2)       // 10240 bytes: A tiles + non-trans B tile
#define BTROW 272                   // trans-B row bytes: 128 fp16 + 8 pad
#define BTMATB (32 * BTROW)         // 8704 bytes trans-B tile
#define OFF_AH 0
#define OFF_AL (MATB)
#define OFF_B  (2 * MATB)
#define GEMM_SMEM 92160             // 3 stages x 30720 (worst case)

template <int EPI, int TRB, int NA, int WS>
__global__ __launch_bounds__(256, 2) void gemm_hh(
    const __half* __restrict__ Agh, const __half* __restrict__ Agl,
    const __half* __restrict__ Bg, const __half* __restrict__ Bgl,
    float* __restrict__ Cf, __half* __restrict__ Ch,
    __half* __restrict__ Cl, const float* __restrict__ E,
    int K, int N, long long sA, long long sB, long long sC, long long sE,
    int causal)
{
    extern __shared__ unsigned char smb[];
    constexpr int BMATB = TRB ? BTMATB : MATB;
    constexpr int STAGEB = 2 * MATB + BMATB;

    const int tid = threadIdx.x;
    const int wid = tid >> 5;
    const int lane = tid & 31;
    const int z = blockIdx.z;

    int bi = blockIdx.y, bj = blockIdx.x;
    if (EPI == EP_SC) {
        int xx = blockIdx.x;
        bi = (int)((sqrtf(8.0f * xx + 1.0f) - 1.0f) * 0.5f);
        while ((bi + 1) * (bi + 2) / 2 <= xx) bi++;
        while (bi * (bi + 1) / 2 > xx) bi--;
        bj = xx - bi * (bi + 1) / 2;
    }
    const int row0 = bi * 128;
    const int col0 = bj * 128;
    const bool diag = (EPI == EP_SC) && (col0 == row0);

    const __half* Ah = Agh + (long long)z * sA;
    const __half* Al = (NA == 2) ? Agl + (long long)z * sA : nullptr;
    const __half* Bm = Bg + (long long)z * sB;
    const __half* Bl = (EPI == EP_HEAD) ? Bgl + (long long)z * sB : nullptr;

    const int kEnd = (causal == 2) ? min(K, row0 + 128) : K;
    const int nch = kEnd >> 5;

    const uint32_t sbase = smem_u32(smb);

    const int ldr = tid >> 1;
    const int ldq = (tid & 1) * 2;
    const size_t aRow = (size_t)(row0 + ldr) * K;
    const size_t bRow = (size_t)(col0 + ldr) * K;     // non-trans only
    const uint32_t sRow = (uint32_t)(ldr * (RPAD * 2));

    const int m0 = (wid >> 2) * 64;
    const int n0 = (wid & 3) * 32;
    const bool wskip = diag && (n0 > m0 + 63);

    uint32_t aoff[4];
#pragma unroll
    for (int mt = 0; mt < 4; mt++)
        aoff[mt] = (uint32_t)((m0 + mt * 16 + (lane & 15)) * (RPAD * 2) +
                              ((lane >> 4) * 8) * 2);
    uint32_t boff[2];
    if (!TRB) {
#pragma unroll
        for (int p = 0; p < 2; p++)
            boff[p] = (uint32_t)((n0 + p * 16 + ((lane >> 4) << 3) + (lane & 7)) *
                                     (RPAD * 2) +
                                 (((lane >> 3) & 1) * 8) * 2);
    } else {
        const int kr = ((lane >> 3) & 1) * 8 + (lane & 7);
#pragma unroll
        for (int p = 0; p < 2; p++) {
            const int nc = n0 + p * 16 + (lane >> 4) * 8;
            boff[p] = (uint32_t)(kr * BTROW + nc * 2);
        }
    }

    float acc[4][4][4] = {};

#define ISSUE(c, st) { \
    const int kk = (c) * 32; \
    const uint32_t sb = sbase + (st) * STAGEB; \
    _Pragma("unroll") for (int u = 0; u < 2; u++) { \
        const int q = ldq + u; \
        cp16(sb + OFF_AH + sRow + q * 16, Ah + aRow + kk + q * 8); \
        if (NA == 2) cp16(sb + OFF_AL + sRow + q * 16, Al + aRow + kk + q * 8); \
        if (!TRB) { \
            cp16(sb + OFF_B + sRow + q * 16, Bm + bRow + kk + q * 8); \
        } else { \
            const int qi = tid * 2 + u; \
            const int brr = qi >> 4, bqc = qi & 15; \
            const size_t g = (size_t)(kk + brr) * N + col0 + bqc * 8; \
            cp16(sb + OFF_B + (uint32_t)(brr * BTROW + bqc * 16), Bm + g); \
        } \
    } }

    // Prologue: 2 chunks in flight
    ISSUE(0, 0);
    CP_COMMIT();
    if (1 < nch) { ISSUE(1, 1); }
    CP_COMMIT();

    int st = 0;
    for (int c = 0; c < nch; c++) {
        cp_wait<1>();
        __syncthreads();
        {
            int st2 = st + 2; if (st2 >= 3) st2 -= 3;
            if (c + 2 < nch) { ISSUE(c + 2, st2); }
        }
        CP_COMMIT();

        const uint32_t stb = sbase + st * STAGEB;
        if (!wskip) {
#pragma unroll
            for (int ks = 0; ks < 2; ks++) {
                const uint32_t ksoA = (uint32_t)(ks * 32);
                const uint32_t ksoB = TRB ? (uint32_t)(ks * 16 * BTROW)
                                          : (uint32_t)(ks * 32);
                uint32_t ahf[4][4], alf[4][4], bf[2][4];
#pragma unroll
                for (int mt = 0; mt < 4; mt++) {
                    ldsm4(ahf[mt], stb + OFF_AH + aoff[mt] + ksoA);
                    if (NA == 2)
                        ldsm4(alf[mt], stb + OFF_AL + aoff[mt] + ksoA);
                }
#pragma unroll
                for (int p = 0; p < 2; p++) {
                    if (!TRB) ldsm4(bf[p], stb + OFF_B + boff[p] + ksoB);
                    else      ldsm4t(bf[p], stb + OFF_B + boff[p] + ksoB);
                }
#pragma unroll
                for (int mt = 0; mt < 4; mt++)
#pragma unroll
                    for (int nt = 0; nt < 4; nt++) {
                        const int p = nt >> 1, h = (nt & 1) * 2;
                        mma16816(acc[mt][nt], ahf[mt], bf[p][h], bf[p][h + 1]);
                    }
                if (NA == 2) {
#pragma unroll
                    for (int mt = 0; mt < 4; mt++)
#pragma unroll
                        for (int nt = 0; nt < 4; nt++) {
                            const int p = nt >> 1, h = (nt & 1) * 2;
                            mma16816(acc[mt][nt], alf[mt], bf[p][h], bf[p][h + 1]);
                        }
                }
            }
        }
        __syncthreads();
        if (++st >= 3) st = 0;
    }
#undef ISSUE

    // ------------------- epilogue -------------------
    float* Cfz = (EPI == EP_SC || EPI == EP_BIAS || EPI == EP_OUT)
                     ? Cf + (long long)z * sC : nullptr;
    __half* Chz = (EPI == EP_Q || EPI == EP_HEAD || EPI == EP_SWISH)
                      ? Ch + (long long)z * sC : nullptr;
    __half* Clz = (!WS && (EPI == EP_Q || EPI == EP_HEAD || EPI == EP_SWISH))
                      ? Cl + (long long)z * sC : nullptr;

#pragma unroll
    for (int mt = 0; mt < 4; mt++) {
#pragma unroll
        for (int nt = 0; nt < 4; nt++) {
#pragma unroll
            for (int half = 0; half < 2; half++) {
                const int r = row0 + m0 + mt * 16 + (lane >> 2) + half * 8;
                const int cc = col0 + n0 + nt * 8 + (lane & 3) * 2;
                float v0 = acc[mt][nt][half * 2];
                float v1 = acc[mt][nt][half * 2 + 1];

                if (EPI == EP_SC) {
                    if (!diag || cc <= r) {
                        v0 *= 0.03125f; v1 *= 0.03125f;
                        *reinterpret_cast<float2*>(&Cfz[(long long)r * N + cc]) =
                            make_float2(v0, v1);
                    }
                } else if (EPI == EP_BIAS) {
                    float2 bb = *reinterpret_cast<const float2*>(&E[cc]);
                    *reinterpret_cast<float2*>(&Cfz[(long long)r * N + cc]) =
                        make_float2(v0 + bb.x, v1 + bb.y);
                } else if (EPI == EP_OUT) {
                    *reinterpret_cast<float2*>(&Cfz[(long long)r * N + cc]) =
                        make_float2(v0, v1);
                } else {
                    if (EPI == EP_HEAD) {
                        // residual q = qh + ql (B operand IS q in [K=S, N=D])
                        __half2 eh = *reinterpret_cast<const __half2*>(
                            &Bm[(long long)r * N + cc]);
                        __half2 el = *reinterpret_cast<const __half2*>(
                            &Bl[(long long)r * N + cc]);
                        v0 += __half2float(eh.x) + __half2float(el.x);
                        v1 += __half2float(eh.y) + __half2float(el.y);
                    }
                    if (EPI == EP_SWISH) {
                        v0 = v0 / (1.0f + expf(-v0));
                        v1 = v1 / (1.0f + expf(-v1));
                    }
                    if (WS) {
                        *reinterpret_cast<__half2*>(&Chz[(long long)r * N + cc]) =
                            __halves2half2(__float2half(v0), __float2half(v1));
                    } else {
                        __half h0, h1, l0, l1;
                        split_h(v0, h0, l0);
                        split_h(v1, h1, l1);
                        *reinterpret_cast<__half2*>(&Chz[(long long)r * N + cc]) =
                            __halves2half2(h0, h1);
                        *reinterpret_cast<__half2*>(&Clz[(long long)r * N + cc]) =
                            __halves2half2(l0, l1);
                    }
                }
            }
        }
    }
}

// ---------------------------------------------------------------------------
// Transpose to single fp16: dst[c][r] = fp16(src[r][c]); optional head sum
// ---------------------------------------------------------------------------
template <bool SUMH>
__global__ void tsingle(const float* __restrict__ S, __half* __restrict__ D,
                        int R, int C)
{
    __shared__ float t[32][33];
    const int tx = threadIdx.x, ty = threadIdx.y;
    const int c0 = blockIdx.x * 32, r0 = blockIdx.y * 32;
#pragma unroll
    for (int i = 0; i < 4; i++) {
        int r = r0 + ty + i * 8;
        float v;
        if (SUMH) {
            v = 0.f;
#pragma unroll
            for (int h = 0; h < 8; h++)
                v += S[(size_t)(h * 1024 + r) * C + c0 + tx];
        } else {
            v = S[(size_t)r * C + c0 + tx];
        }
        t[ty + i * 8][tx] = v;
    }
    __syncthreads();
#pragma unroll
    for (int i = 0; i < 4; i++) {
        int orow = c0 + ty + i * 8;
        D[(size_t)orow * R + r0 + tx] = __float2half(t[tx][ty + i * 8]);
    }
}

// ---------------------------------------------------------------------------
// Elementwise 2-term split (fp16)
// ---------------------------------------------------------------------------
__global__ void split_ew(const float* __restrict__ X, __half* __restrict__ H,
                         __half* __restrict__ L)
{
    size_t i = ((size_t)blockIdx.x * 256 + threadIdx.x);
    float4 v = reinterpret_cast<const float4*>(X)[i];
    __half h0, h1, h2, h3, l0, l1, l2, l3;
    split_h(v.x, h0, l0); split_h(v.y, h1, l1);
    split_h(v.z, h2, l2); split_h(v.w, h3, l3);
    reinterpret_cast<__half2*>(H)[i * 2]     = __halves2half2(h0, h1);
    reinterpret_cast<__half2*>(H)[i * 2 + 1] = __halves2half2(h2, h3);
    reinterpret_cast<__half2*>(L)[i * 2]     = __halves2half2(l0, l1);
    reinterpret_cast<__half2*>(L)[i * 2 + 1] = __halves2half2(l2, l3);
}

// ---------------------------------------------------------------------------
// Reductions
// ---------------------------------------------------------------------------
__device__ __forceinline__ float warpMax(float v) {
#pragma unroll
    for (int o = 16; o; o >>= 1) v = fmaxf(v, __shfl_xor_sync(0xffffffffu, v, o));
    return v;
}
__device__ __forceinline__ float warpSum(float v) {
#pragma unroll
    for (int o = 16; o; o >>= 1) v += __shfl_xor_sync(0xffffffffu, v, o);
    return v;
}

// Causal softmax; writes SINGLE fp16 probs only for cols < kLim.
__global__ __launch_bounds__(256) void softmax_single(
    const float* __restrict__ Sc, __half* __restrict__ Ph)
{
    const int r = blockIdx.x & (SS - 1);
    const int kLim = ((r >> 7) + 1) << 7;
    const float* row = Sc + (long long)blockIdx.x * SS;
    __half* oh = Ph + (long long)blockIdx.x * SS;
    const int tid = threadIdx.x, lane = tid & 31, w = tid >> 5;
    __shared__ float red[32];

    const int c0 = tid * 4;
    const int c1 = 1024 + tid * 4;
    float4 v0 = make_float4(NEGV, NEGV, NEGV, NEGV);
    float4 v1 = make_float4(NEGV, NEGV, NEGV, NEGV);
    if (c0 < kLim) v0 = reinterpret_cast<const float4*>(row)[tid];
    if (c1 < kLim) v1 = reinterpret_cast<const float4*>(row)[tid + 256];

    float m = -3.4e38f;
    if (c0 + 0 <= r) m = fmaxf(m, v0.x);
    if (c0 + 1 <= r) m = fmaxf(m, v0.y);
    if (c0 + 2 <= r) m = fmaxf(m, v0.z);
    if (c0 + 3 <= r) m = fmaxf(m, v0.w);
    if (c1 + 0 <= r) m = fmaxf(m, v1.x);
    if (c1 + 1 <= r) m = fmaxf(m, v1.y);
    if (c1 + 2 <= r) m = fmaxf(m, v1.z);
    if (c1 + 3 <= r) m = fmaxf(m, v1.w);
    m = warpMax(m);
    if (lane == 0) red[w] = m;
    __syncthreads();
    if (tid < 32) { float x = (tid < 8) ? red[tid] : -3.4e38f; x = warpMax(x);
                    if (tid == 0) red[0] = x; }
    __syncthreads();
    m = red[0];
    __syncthreads();

    float e[8];
    e[0] = (c0 + 0 <= r) ? expf(v0.x - m) : 0.f;
    e[1] = (c0 + 1 <= r) ? expf(v0.y - m) : 0.f;
    e[2] = (c0 + 2 <= r) ? expf(v0.z - m) : 0.f;
    e[3] = (c0 + 3 <= r) ? expf(v0.w - m) : 0.f;
    e[4] = (c1 + 0 <= r) ? expf(v1.x - m) : 0.f;
    e[5] = (c1 + 1 <= r) ? expf(v1.y - m) : 0.f;
    e[6] = (c1 + 2 <= r) ? expf(v1.z - m) : 0.f;
    e[7] = (c1 + 3 <= r) ? expf(v1.w - m) : 0.f;
    float s = e[0] + e[1] + e[2] + e[3] + e[4] + e[5] + e[6] + e[7];
    s = warpSum(s);
    if (lane == 0) red[w] = s;
    __syncthreads();
    if (tid < 32) { float x = (tid < 8) ? red[tid] : 0.f; x = warpSum(x);
                    if (tid == 0) red[0] = x; }
    __syncthreads();
    const float inv = 1.0f / red[0];

    __half h[8];
#pragma unroll
    for (int u = 0; u < 8; u++) h[u] = __float2half(e[u] * inv);
    __half2* phh = reinterpret_cast<__half2*>(oh);
    if (c0 < kLim) {
        phh[tid * 2]     = __halves2half2(h[0], h[1]);
        phh[tid * 2 + 1] = __halves2half2(h[2], h[3]);
    }
    if (c1 < kLim) {
        phh[(tid + 256) * 2]     = __halves2half2(h[4], h[5]);
        phh[(tid + 256) * 2 + 1] = __halves2half2(h[6], h[7]);
    }
}

// LayerNorm -> single fp16. One block per row (1024 cols).
__global__ __launch_bounds__(256) void ln_single(
    const float* __restrict__ Hf, __half* __restrict__ Oh)
{
    const float* row = Hf + (long long)blockIdx.x * DD;
    __half* oh = Oh + (long long)blockIdx.x * DD;
    const int tid = threadIdx.x, lane = tid & 31, w = tid >> 5;
    __shared__ float r1[32], r2[32];

    float4 v = reinterpret_cast<const float4*>(row)[tid];
    float s = v.x + v.y + v.z + v.w;
    float s2 = v.x * v.x + v.y * v.y + v.z * v.z + v.w * v.w;
    s = warpSum(s); s2 = warpSum(s2);
    if (lane == 0) { r1[w] = s; r2[w] = s2; }
    __syncthreads();
    if (tid < 32) {
        float a = (tid < 8) ? r1[tid] : 0.f;
        float b = (tid < 8) ? r2[tid] : 0.f;
        a = warpSum(a); b = warpSum(b);
        if (tid == 0) { r1[0] = a; r2[0] = b; }
    }
    __syncthreads();
    const float mean = r1[0] * (1.0f / DD);
    const float msq = r2[0] * (1.0f / DD);
    const float inv = rsqrtf(msq - mean * mean + EPSV);

    reinterpret_cast<__half2*>(oh)[tid * 2] = __halves2half2(
        __float2half((v.x - mean) * inv), __float2half((v.y - mean) * inv));
    reinterpret_cast<__half2*>(oh)[tid * 2 + 1] = __halves2half2(
        __float2half((v.z - mean) * inv), __float2half((v.w - mean) * inv));
}

// ---------------------------------------------------------------------------
// Launch
// ---------------------------------------------------------------------------
extern "C" void kernel_launch(void* const* d_in, const int* in_sizes, int n_in,
                              void* d_out, int out_size)
{
    (void)in_sizes; (void)n_in; (void)out_size;
    const float* x     = (const float*)d_in[0];
    const float* wi    = (const float*)d_in[2];
    const float* okern = (const float*)d_in[3];
    const float* obias = (const float*)d_in[4];
    float* out = (float*)d_out;

    unsigned char* base;
    cudaGetSymbolAddress((void**)&base, g_scratch);
    float* sc  = (float*)(base + O_SC);
    float* hhf = (float*)(base + O_HHF);
    __half* qh  = (__half*)(base + O_QH);
    __half* ql  = (__half*)(base + O_QL);
    __half* xh  = (__half*)(base + O_XH);
    __half* xl  = (__half*)(base + O_XL);
    __half* Pph = (__half*)(base + O_PH);
    __half* hdh = (__half*)(base + O_HDH);
    __half* hnh = (__half*)(base + O_HNH);
    __half* fh  = (__half*)(base + O_FH);
    __half* wT  = (__half*)(base + O_WT);
    __half* wsT = (__half*)(base + O_WS);

    cudaFuncSetAttribute(gemm_hh<EP_Q, 0, 2, 0>,     cudaFuncAttributeMaxDynamicSharedMemorySize, GEMM_SMEM);
    cudaFuncSetAttribute(gemm_hh<EP_SC, 0, 2, 0>,    cudaFuncAttributeMaxDynamicSharedMemorySize, GEMM_SMEM);
    cudaFuncSetAttribute(gemm_hh<EP_HEAD, 1, 1, 1>,  cudaFuncAttributeMaxDynamicSharedMemorySize, GEMM_SMEM);
    cudaFuncSetAttribute(gemm_hh<EP_BIAS, 0, 1, 0>,  cudaFuncAttributeMaxDynamicSharedMemorySize, GEMM_SMEM);
    cudaFuncSetAttribute(gemm_hh<EP_SWISH, 0, 1, 1>, cudaFuncAttributeMaxDynamicSharedMemorySize, GEMM_SMEM);
    cudaFuncSetAttribute(gemm_hh<EP_OUT, 0, 1, 0>,   cudaFuncAttributeMaxDynamicSharedMemorySize, GEMM_SMEM);

    const long long sSD = (long long)SS * DD;   // 2,097,152
    const long long sSS = (long long)SS * SS;   // 4,194,304
    dim3 tb(32, 8);

    // wi^T single, Wsum^T single, x 2-term split
    tsingle<false><<<dim3(32, 32, 1), tb>>>(wi, wT, DD, DD);
    tsingle<true><<<dim3(32, 32, 1), tb>>>(okern, wsT, DD, DD);
    split_ew<<<(BSR * DD) / 1024, 256>>>(x, xh, xl);

    // q = x @ wi  (2-term split out; residual later reconstructed as qh+ql)
    gemm_hh<EP_Q, 0, 2, 0><<<dim3(8, 32, 1), 256, GEMM_SMEM>>>(
        xh, xl, wT, nullptr, nullptr, qh, ql, nullptr, DD, DD, 0, 0, 0, 0, 0);

    // scores = (q @ q^T)/32, lower triangle only (136 tiles per batch)
    gemm_hh<EP_SC, 0, 2, 0><<<dim3(136, 1, 2), 256, GEMM_SMEM>>>(
        qh, ql, qh, nullptr, sc, nullptr, nullptr, nullptr,
        DD, SS, sSD, sSD, sSS, 0, 1);

    // causal softmax -> single fp16 probs
    softmax_single<<<SB * SS, 256>>>(sc, Pph);

    // head = q + P @ q  (single x single; trans-B; single fp16 out)
    gemm_hh<EP_HEAD, 1, 1, 1><<<dim3(8, 16, 2), 256, GEMM_SMEM>>>(
        Pph, nullptr, qh, ql, nullptr, hdh, nullptr, nullptr,
        SS, DD, sSS, sSD, sSD, sSD, 2);

    // h = head @ Wsum + bias  fp32  (single-A)
    gemm_hh<EP_BIAS, 0, 1, 0><<<dim3(8, 32, 1), 256, GEMM_SMEM>>>(
        hdh, nullptr, wsT, nullptr, hhf, nullptr, nullptr, obias,
        DD, DD, 0, 0, 0, 0, 0);

    // layernorm -> single fp16
    ln_single<<<BSR, 256>>>(hhf, hnh);

    // f = swish(h @ wi)  (single-A; single fp16 out)
    gemm_hh<EP_SWISH, 0, 1, 1><<<dim3(8, 32, 1), 256, GEMM_SMEM>>>(
        hnh, nullptr, wT, nullptr, nullptr, fh, nullptr, nullptr,
        DD, DD, 0, 0, 0, 0, 0);

    // out = f @ wi  fp32  (single-A)
    gemm_hh<EP_OUT, 0, 1, 0><<<dim3(8, 32, 1), 256, GEMM_SMEM>>>(
        fh, nullptr, wT, nullptr, out, nullptr, nullptr, nullptr,
        DD, DD, 0, 0, 0, 0, 0);
}

// round 16
// speedup vs baseline: 1.5890x; 1.0711x over previous
#include <cuda_runtime.h>
#include <cuda_fp16.h>
#include <stdint.h>
#include <math.h>

#define SB 2
#define SS 2048
#define DD 1024
#define BSR 4096
#define NEGV (-1e10f)
#define EPSV 1e-5f

// ---------------------------------------------------------------------------
// Scratch carve-out (one big device global; no allocation allowed)
// ---------------------------------------------------------------------------
__device__ __align__(256) unsigned char g_scratch[209715200ULL];  // 200 MB

#define O_QH   16777216ULL     // q hi fp16         [4096,1024]
#define O_QL   25165824ULL     // q lo fp16
#define O_XH   50331648ULL     // x split
#define O_XL   58720256ULL
#define O_SC   67108864ULL     // scores fp32       [2][2048][2048]
#define O_PH   100663296ULL    // softmax probs (single fp16)
#define O_HDH  134217728ULL    // head single fp16
#define O_HHF  150994944ULL    // h fp32 (pre-LN)
#define O_HNH  167772160ULL    // h single fp16 (post-LN)
#define O_FH   184549376ULL    // swish output single fp16
#define O_WT   201326592ULL    // wi^T single fp16  [1024,1024]
#define O_WS   205520896ULL    // Wsum^T single fp16

// ---------------------------------------------------------------------------
// Portable sm_80+ primitives: cp.async, ldmatrix, fp16 mma.sync
// ---------------------------------------------------------------------------
__device__ __forceinline__ uint32_t smem_u32(const void* p) {
    uint32_t a;
    asm("{ .reg .u64 t; cvta.to.shared.u64 t, %1; cvt.u32.u64 %0, t; }"
        : "=r"(a) : "l"(p));
    return a;
}
__device__ __forceinline__ void cp16(uint32_t s, const void* g) {
    asm volatile("cp.async.cg.shared.global [%0], [%1], 16;" :: "r"(s), "l"(g));
}
#define CP_COMMIT() asm volatile("cp.async.commit_group;" ::: "memory")
template <int N> __device__ __forceinline__ void cp_wait() {
    asm volatile("cp.async.wait_group %0;" :: "n"(N) : "memory");
}
__device__ __forceinline__ void ldsm4(uint32_t (&r)[4], uint32_t a) {
    asm volatile("ldmatrix.sync.aligned.m8n8.x4.shared.b16 {%0,%1,%2,%3}, [%4];"
                 : "=r"(r[0]), "=r"(r[1]), "=r"(r[2]), "=r"(r[3]) : "r"(a));
}
__device__ __forceinline__ void ldsm4t(uint32_t (&r)[4], uint32_t a) {
    asm volatile("ldmatrix.sync.aligned.m8n8.x4.trans.shared.b16 {%0,%1,%2,%3}, [%4];"
                 : "=r"(r[0]), "=r"(r[1]), "=r"(r[2]), "=r"(r[3]) : "r"(a));
}
__device__ __forceinline__ void mma16816(float (&c)[4], const uint32_t (&a)[4],
                                         uint32_t b0, uint32_t b1) {
    asm volatile(
        "mma.sync.aligned.m16n8k16.row.col.f32.f16.f16.f32 "
        "{%0,%1,%2,%3}, {%4,%5,%6,%7}, {%8,%9}, {%0,%1,%2,%3};"
        : "+f"(c[0]), "+f"(c[1]), "+f"(c[2]), "+f"(c[3])
        : "r"(a[0]), "r"(a[1]), "r"(a[2]), "r"(a[3]), "r"(b0), "r"(b1));
}

__device__ __forceinline__ void split_h(float v, __half& h, __half& l) {
    h = __float2half(v);
    l = __float2half(v - __half2float(h));
}

// ---------------------------------------------------------------------------
// GEMM: C[M,N] = A[M,K] @ B^T. A fp16 with NA terms (2 = hi/lo split, 1 =
// single), B single fp16. TRB=1 -> B stored [K,N] (ldmatrix.trans).
// WS=1 -> epilogue writes only the hi fp16 plane (no low plane).
// CTA tile 128x128, 8 warps (2m x 4n of 64x32), K-chunk 32, 3-stage
// cp.async pipeline with wait_group<1>, 2 CTA/SM.
// ---------------------------------------------------------------------------
enum { EP_Q = 0, EP_SC = 1, EP_HEAD = 2, EP_BIAS = 3, EP_SWISH = 4, EP_OUT = 5 };

#define RPAD 40
#define MATB (128 * RPAD * 2)       // 10240 bytes: A tiles + non-trans B tile
#define BTROW 272                   // trans-B row bytes: 128 fp16 + 8 pad
#define BTMATB (32 * BTROW)         // 8704 bytes trans-B tile
#define OFF_AH 0
#define OFF_AL (MATB)
#define OFF_B  (2 * MATB)
#define GEMM_SMEM 92160             // 3 stages x 30720 (worst case)

template <int EPI, int TRB, int NA, int WS>
__global__ __launch_bounds__(256, 2) void gemm_hh(
    const __half* __restrict__ Agh, const __half* __restrict__ Agl,
    const __half* __restrict__ Bg, const __half* __restrict__ Bgl,
    float* __restrict__ Cf, __half* __restrict__ Ch,
    __half* __restrict__ Cl, const float* __restrict__ E,
    int K, int N, long long sA, long long sB, long long sC, long long sE,
    int causal)
{
    extern __shared__ unsigned char smb[];
    constexpr int BMATB = TRB ? BTMATB : MATB;
    constexpr int STAGEB = 2 * MATB + BMATB;

    const int tid = threadIdx.x;
    const int wid = tid >> 5;
    const int lane = tid & 31;
    const int z = blockIdx.z;

    int bi = blockIdx.y, bj = blockIdx.x;
    if (EPI == EP_SC) {
        int xx = blockIdx.x;
        bi = (int)((sqrtf(8.0f * xx + 1.0f) - 1.0f) * 0.5f);
        while ((bi + 1) * (bi + 2) / 2 <= xx) bi++;
        while (bi * (bi + 1) / 2 > xx) bi--;
        bj = xx - bi * (bi + 1) / 2;
    }
    const int row0 = bi * 128;
    const int col0 = bj * 128;
    const bool diag = (EPI == EP_SC) && (col0 == row0);

    const __half* Ah = Agh + (long long)z * sA;
    const __half* Al = (NA == 2) ? Agl + (long long)z * sA : nullptr;
    const __half* Bm = Bg + (long long)z * sB;
    const __half* Bl = (EPI == EP_HEAD) ? Bgl + (long long)z * sB : nullptr;

    const int kEnd = (causal == 2) ? min(K, row0 + 128) : K;
    const int nch = kEnd >> 5;

    const uint32_t sbase = smem_u32(smb);

    const int ldr = tid >> 1;
    const int ldq = (tid & 1) * 2;
    const size_t aRow = (size_t)(row0 + ldr) * K;
    const size_t bRow = (size_t)(col0 + ldr) * K;     // non-trans only
    const uint32_t sRow = (uint32_t)(ldr * (RPAD * 2));

    const int m0 = (wid >> 2) * 64;
    const int n0 = (wid & 3) * 32;
    const bool wskip = diag && (n0 > m0 + 63);

    uint32_t aoff[4];
#pragma unroll
    for (int mt = 0; mt < 4; mt++)
        aoff[mt] = (uint32_t)((m0 + mt * 16 + (lane & 15)) * (RPAD * 2) +
                              ((lane >> 4) * 8) * 2);
    uint32_t boff[2];
    if (!TRB) {
#pragma unroll
        for (int p = 0; p < 2; p++)
            boff[p] = (uint32_t)((n0 + p * 16 + ((lane >> 4) << 3) + (lane & 7)) *
                                     (RPAD * 2) +
                                 (((lane >> 3) & 1) * 8) * 2);
    } else {
        const int kr = ((lane >> 3) & 1) * 8 + (lane & 7);
#pragma unroll
        for (int p = 0; p < 2; p++) {
            const int nc = n0 + p * 16 + (lane >> 4) * 8;
            boff[p] = (uint32_t)(kr * BTROW + nc * 2);
        }
    }

    float acc[4][4][4] = {};

#define ISSUE(c, st) { \
    const int kk = (c) * 32; \
    const uint32_t sb = sbase + (st) * STAGEB; \
    _Pragma("unroll") for (int u = 0; u < 2; u++) { \
        const int q = ldq + u; \
        cp16(sb + OFF_AH + sRow + q * 16, Ah + aRow + kk + q * 8); \
        if (NA == 2) cp16(sb + OFF_AL + sRow + q * 16, Al + aRow + kk + q * 8); \
        if (!TRB) { \
            cp16(sb + OFF_B + sRow + q * 16, Bm + bRow + kk + q * 8); \
        } else { \
            const int qi = tid * 2 + u; \
            const int brr = qi >> 4, bqc = qi & 15; \
            const size_t g = (size_t)(kk + brr) * N + col0 + bqc * 8; \
            cp16(sb + OFF_B + (uint32_t)(brr * BTROW + bqc * 16), Bm + g); \
        } \
    } }

    // Prologue: 2 chunks in flight
    ISSUE(0, 0);
    CP_COMMIT();
    if (1 < nch) { ISSUE(1, 1); }
    CP_COMMIT();

    int st = 0;
    for (int c = 0; c < nch; c++) {
        cp_wait<1>();
        __syncthreads();
        {
            int st2 = st + 2; if (st2 >= 3) st2 -= 3;
            if (c + 2 < nch) { ISSUE(c + 2, st2); }
        }
        CP_COMMIT();

        const uint32_t stb = sbase + st * STAGEB;
        if (!wskip) {
#pragma unroll
            for (int ks = 0; ks < 2; ks++) {
                const uint32_t ksoA = (uint32_t)(ks * 32);
                const uint32_t ksoB = TRB ? (uint32_t)(ks * 16 * BTROW)
                                          : (uint32_t)(ks * 32);
                uint32_t ahf[4][4], alf[4][4], bf[2][4];
#pragma unroll
                for (int mt = 0; mt < 4; mt++) {
                    ldsm4(ahf[mt], stb + OFF_AH + aoff[mt] + ksoA);
                    if (NA == 2)
                        ldsm4(alf[mt], stb + OFF_AL + aoff[mt] + ksoA);
                }
#pragma unroll
                for (int p = 0; p < 2; p++) {
                    if (!TRB) ldsm4(bf[p], stb + OFF_B + boff[p] + ksoB);
                    else      ldsm4t(bf[p], stb + OFF_B + boff[p] + ksoB);
                }
#pragma unroll
                for (int mt = 0; mt < 4; mt++)
#pragma unroll
                    for (int nt = 0; nt < 4; nt++) {
                        const int p = nt >> 1, h = (nt & 1) * 2;
                        mma16816(acc[mt][nt], ahf[mt], bf[p][h], bf[p][h + 1]);
                    }
                if (NA == 2) {
#pragma unroll
                    for (int mt = 0; mt < 4; mt++)
#pragma unroll
                        for (int nt = 0; nt < 4; nt++) {
                            const int p = nt >> 1, h = (nt & 1) * 2;
                            mma16816(acc[mt][nt], alf[mt], bf[p][h], bf[p][h + 1]);
                        }
                }
            }
        }
        __syncthreads();
        if (++st >= 3) st = 0;
    }
#undef ISSUE

    // ------------------- epilogue -------------------
    float* Cfz = (EPI == EP_SC || EPI == EP_BIAS || EPI == EP_OUT)
                     ? Cf + (long long)z * sC : nullptr;
    __half* Chz = (EPI == EP_Q || EPI == EP_HEAD || EPI == EP_SWISH)
                      ? Ch + (long long)z * sC : nullptr;
    __half* Clz = (!WS && (EPI == EP_Q || EPI == EP_HEAD || EPI == EP_SWISH))
                      ? Cl + (long long)z * sC : nullptr;

#pragma unroll
    for (int mt = 0; mt < 4; mt++) {
#pragma unroll
        for (int nt = 0; nt < 4; nt++) {
#pragma unroll
            for (int half = 0; half < 2; half++) {
                const int r = row0 + m0 + mt * 16 + (lane >> 2) + half * 8;
                const int cc = col0 + n0 + nt * 8 + (lane & 3) * 2;
                float v0 = acc[mt][nt][half * 2];
                float v1 = acc[mt][nt][half * 2 + 1];

                if (EPI == EP_SC) {
                    if (!diag || cc <= r) {
                        v0 *= 0.03125f; v1 *= 0.03125f;
                        *reinterpret_cast<float2*>(&Cfz[(long long)r * N + cc]) =
                            make_float2(v0, v1);
                    }
                } else if (EPI == EP_BIAS) {
                    float2 bb = *reinterpret_cast<const float2*>(&E[cc]);
                    *reinterpret_cast<float2*>(&Cfz[(long long)r * N + cc]) =
                        make_float2(v0 + bb.x, v1 + bb.y);
                } else if (EPI == EP_OUT) {
                    *reinterpret_cast<float2*>(&Cfz[(long long)r * N + cc]) =
                        make_float2(v0, v1);
                } else {
                    if (EPI == EP_HEAD) {
                        // residual q = qh + ql (B operand IS q in [K=S, N=D])
                        __half2 eh = *reinterpret_cast<const __half2*>(
                            &Bm[(long long)r * N + cc]);
                        __half2 el = *reinterpret_cast<const __half2*>(
                            &Bl[(long long)r * N + cc]);
                        v0 += __half2float(eh.x) + __half2float(el.x);
                        v1 += __half2float(eh.y) + __half2float(el.y);
                    }
                    if (EPI == EP_SWISH) {
                        v0 = v0 / (1.0f + expf(-v0));
                        v1 = v1 / (1.0f + expf(-v1));
                    }
                    if (WS) {
                        *reinterpret_cast<__half2*>(&Chz[(long long)r * N + cc]) =
                            __halves2half2(__float2half(v0), __float2half(v1));
                    } else {
                        __half h0, h1, l0, l1;
                        split_h(v0, h0, l0);
                        split_h(v1, h1, l1);
                        *reinterpret_cast<__half2*>(&Chz[(long long)r * N + cc]) =
                            __halves2half2(h0, h1);
                        *reinterpret_cast<__half2*>(&Clz[(long long)r * N + cc]) =
                            __halves2half2(l0, l1);
                    }
                }
            }
        }
    }
}

// ---------------------------------------------------------------------------
// Transpose to single fp16: dst[c][r] = fp16(src[r][c]); optional head sum
// ---------------------------------------------------------------------------
template <bool SUMH>
__global__ void tsingle(const float* __restrict__ S, __half* __restrict__ D,
                        int R, int C)
{
    __shared__ float t[32][33];
    const int tx = threadIdx.x, ty = threadIdx.y;
    const int c0 = blockIdx.x * 32, r0 = blockIdx.y * 32;
#pragma unroll
    for (int i = 0; i < 4; i++) {
        int r = r0 + ty + i * 8;
        float v;
        if (SUMH) {
            v = 0.f;
#pragma unroll
            for (int h = 0; h < 8; h++)
                v += S[(size_t)(h * 1024 + r) * C + c0 + tx];
        } else {
            v = S[(size_t)r * C + c0 + tx];
        }
        t[ty + i * 8][tx] = v;
    }
    __syncthreads();
#pragma unroll
    for (int i = 0; i < 4; i++) {
        int orow = c0 + ty + i * 8;
        D[(size_t)orow * R + r0 + tx] = __float2half(t[tx][ty + i * 8]);
    }
}

// ---------------------------------------------------------------------------
// Elementwise 2-term split (fp16)
// ---------------------------------------------------------------------------
__global__ void split_ew(const float* __restrict__ X, __half* __restrict__ H,
                         __half* __restrict__ L)
{
    size_t i = ((size_t)blockIdx.x * 256 + threadIdx.x);
    float4 v = reinterpret_cast<const float4*>(X)[i];
    __half h0, h1, h2, h3, l0, l1, l2, l3;
    split_h(v.x, h0, l0); split_h(v.y, h1, l1);
    split_h(v.z, h2, l2); split_h(v.w, h3, l3);
    reinterpret_cast<__half2*>(H)[i * 2]     = __halves2half2(h0, h1);
    reinterpret_cast<__half2*>(H)[i * 2 + 1] = __halves2half2(h2, h3);
    reinterpret_cast<__half2*>(L)[i * 2]     = __halves2half2(l0, l1);
    reinterpret_cast<__half2*>(L)[i * 2 + 1] = __halves2half2(l2, l3);
}

// ---------------------------------------------------------------------------
// Reductions
// ---------------------------------------------------------------------------
__device__ __forceinline__ float warpMax(float v) {
#pragma unroll
    for (int o = 16; o; o >>= 1) v = fmaxf(v, __shfl_xor_sync(0xffffffffu, v, o));
    return v;
}
__device__ __forceinline__ float warpSum(float v) {
#pragma unroll
    for (int o = 16; o; o >>= 1) v += __shfl_xor_sync(0xffffffffu, v, o);
    return v;
}

// Causal softmax; writes SINGLE fp16 probs only for cols < kLim.
__global__ __launch_bounds__(256) void softmax_single(
    const float* __restrict__ Sc, __half* __restrict__ Ph)
{
    const int r = blockIdx.x & (SS - 1);
    const int kLim = ((r >> 7) + 1) << 7;
    const float* row = Sc + (long long)blockIdx.x * SS;
    __half* oh = Ph + (long long)blockIdx.x * SS;
    const int tid = threadIdx.x, lane = tid & 31, w = tid >> 5;
    __shared__ float red[32];

    const int c0 = tid * 4;
    const int c1 = 1024 + tid * 4;
    float4 v0 = make_float4(NEGV, NEGV, NEGV, NEGV);
    float4 v1 = make_float4(NEGV, NEGV, NEGV, NEGV);
    if (c0 < kLim) v0 = reinterpret_cast<const float4*>(row)[tid];
    if (c1 < kLim) v1 = reinterpret_cast<const float4*>(row)[tid + 256];

    float m = -3.4e38f;
    if (c0 + 0 <= r) m = fmaxf(m, v0.x);
    if (c0 + 1 <= r) m = fmaxf(m, v0.y);
    if (c0 + 2 <= r) m = fmaxf(m, v0.z);
    if (c0 + 3 <= r) m = fmaxf(m, v0.w);
    if (c1 + 0 <= r) m = fmaxf(m, v1.x);
    if (c1 + 1 <= r) m = fmaxf(m, v1.y);
    if (c1 + 2 <= r) m = fmaxf(m, v1.z);
    if (c1 + 3 <= r) m = fmaxf(m, v1.w);
    m = warpMax(m);
    if (lane == 0) red[w] = m;
    __syncthreads();
    if (tid < 32) { float x = (tid < 8) ? red[tid] : -3.4e38f; x = warpMax(x);
                    if (tid == 0) red[0] = x; }
    __syncthreads();
    m = red[0];
    __syncthreads();

    float e[8];
    e[0] = (c0 + 0 <= r) ? expf(v0.x - m) : 0.f;
    e[1] = (c0 + 1 <= r) ? expf(v0.y - m) : 0.f;
    e[2] = (c0 + 2 <= r) ? expf(v0.z - m) : 0.f;
    e[3] = (c0 + 3 <= r) ? expf(v0.w - m) : 0.f;
    e[4] = (c1 + 0 <= r) ? expf(v1.x - m) : 0.f;
    e[5] = (c1 + 1 <= r) ? expf(v1.y - m) : 0.f;
    e[6] = (c1 + 2 <= r) ? expf(v1.z - m) : 0.f;
    e[7] = (c1 + 3 <= r) ? expf(v1.w - m) : 0.f;
    float s = e[0] + e[1] + e[2] + e[3] + e[4] + e[5] + e[6] + e[7];
    s = warpSum(s);
    if (lane == 0) red[w] = s;
    __syncthreads();
    if (tid < 32) { float x = (tid < 8) ? red[tid] : 0.f; x = warpSum(x);
                    if (tid == 0) red[0] = x; }
    __syncthreads();
    const float inv = 1.0f / red[0];

    __half h[8];
#pragma unroll
    for (int u = 0; u < 8; u++) h[u] = __float2half(e[u] * inv);
    __half2* phh = reinterpret_cast<__half2*>(oh);
    if (c0 < kLim) {
        phh[tid * 2]     = __halves2half2(h[0], h[1]);
        phh[tid * 2 + 1] = __halves2half2(h[2], h[3]);
    }
    if (c1 < kLim) {
        phh[(tid + 256) * 2]     = __halves2half2(h[4], h[5]);
        phh[(tid + 256) * 2 + 1] = __halves2half2(h[6], h[7]);
    }
}

// LayerNorm -> single fp16. One block per row (1024 cols).
__global__ __launch_bounds__(256) void ln_single(
    const float* __restrict__ Hf, __half* __restrict__ Oh)
{
    const float* row = Hf + (long long)blockIdx.x * DD;
    __half* oh = Oh + (long long)blockIdx.x * DD;
    const int tid = threadIdx.x, lane = tid & 31, w = tid >> 5;
    __shared__ float r1[32], r2[32];

    float4 v = reinterpret_cast<const float4*>(row)[tid];
    float s = v.x + v.y + v.z + v.w;
    float s2 = v.x * v.x + v.y * v.y + v.z * v.z + v.w * v.w;
    s = warpSum(s); s2 = warpSum(s2);
    if (lane == 0) { r1[w] = s; r2[w] = s2; }
    __syncthreads();
    if (tid < 32) {
        float a = (tid < 8) ? r1[tid] : 0.f;
        float b = (tid < 8) ? r2[tid] : 0.f;
        a = warpSum(a); b = warpSum(b);
        if (tid == 0) { r1[0] = a; r2[0] = b; }
    }
    __syncthreads();
    const float mean = r1[0] * (1.0f / DD);
    const float msq = r2[0] * (1.0f / DD);
    const float inv = rsqrtf(msq - mean * mean + EPSV);

    reinterpret_cast<__half2*>(oh)[tid * 2] = __halves2half2(
        __float2half((v.x - mean) * inv), __float2half((v.y - mean) * inv));
    reinterpret_cast<__half2*>(oh)[tid * 2 + 1] = __halves2half2(
        __float2half((v.z - mean) * inv), __float2half((v.w - mean) * inv));
}

// ---------------------------------------------------------------------------
// Launch
// ---------------------------------------------------------------------------
extern "C" void kernel_launch(void* const* d_in, const int* in_sizes, int n_in,
                              void* d_out, int out_size)
{
    (void)in_sizes; (void)n_in; (void)out_size;
    const float* x     = (const float*)d_in[0];
    const float* wi    = (const float*)d_in[2];
    const float* okern = (const float*)d_in[3];
    const float* obias = (const float*)d_in[4];
    float* out = (float*)d_out;

    unsigned char* base;
    cudaGetSymbolAddress((void**)&base, g_scratch);
    float* sc  = (float*)(base + O_SC);
    float* hhf = (float*)(base + O_HHF);
    __half* qh  = (__half*)(base + O_QH);
    __half* ql  = (__half*)(base + O_QL);
    __half* xh  = (__half*)(base + O_XH);
    __half* xl  = (__half*)(base + O_XL);
    __half* Pph = (__half*)(base + O_PH);
    __half* hdh = (__half*)(base + O_HDH);
    __half* hnh = (__half*)(base + O_HNH);
    __half* fh  = (__half*)(base + O_FH);
    __half* wT  = (__half*)(base + O_WT);
    __half* wsT = (__half*)(base + O_WS);

    cudaFuncSetAttribute(gemm_hh<EP_Q, 0, 2, 0>,     cudaFuncAttributeMaxDynamicSharedMemorySize, GEMM_SMEM);
    cudaFuncSetAttribute(gemm_hh<EP_SC, 0, 1, 0>,    cudaFuncAttributeMaxDynamicSharedMemorySize, GEMM_SMEM);
    cudaFuncSetAttribute(gemm_hh<EP_HEAD, 1, 1, 1>,  cudaFuncAttributeMaxDynamicSharedMemorySize, GEMM_SMEM);
    cudaFuncSetAttribute(gemm_hh<EP_BIAS, 0, 1, 0>,  cudaFuncAttributeMaxDynamicSharedMemorySize, GEMM_SMEM);
    cudaFuncSetAttribute(gemm_hh<EP_SWISH, 0, 1, 1>, cudaFuncAttributeMaxDynamicSharedMemorySize, GEMM_SMEM);
    cudaFuncSetAttribute(gemm_hh<EP_OUT, 0, 1, 0>,   cudaFuncAttributeMaxDynamicSharedMemorySize, GEMM_SMEM);

    const long long sSD = (long long)SS * DD;   // 2,097,152
    const long long sSS = (long long)SS * SS;   // 4,194,304
    dim3 tb(32, 8);

    // wi^T single, Wsum^T single, x 2-term split
    tsingle<false><<<dim3(32, 32, 1), tb>>>(wi, wT, DD, DD);
    tsingle<true><<<dim3(32, 32, 1), tb>>>(okern, wsT, DD, DD);
    split_ew<<<(BSR * DD) / 1024, 256>>>(x, xh, xl);

    // q = x @ wi  (2-term split out; residual later reconstructed as qh+ql)
    gemm_hh<EP_Q, 0, 2, 0><<<dim3(8, 32, 1), 256, GEMM_SMEM>>>(
        xh, xl, wT, nullptr, nullptr, qh, ql, nullptr, DD, DD, 0, 0, 0, 0, 0);

    // scores = (q @ q^T)/32, lower triangle only; single-A x single-B
    gemm_hh<EP_SC, 0, 1, 0><<<dim3(136, 1, 2), 256, GEMM_SMEM>>>(
        qh, nullptr, qh, nullptr, sc, nullptr, nullptr, nullptr,
        DD, SS, sSD, sSD, sSS, 0, 1);

    // causal softmax -> single fp16 probs
    softmax_single<<<SB * SS, 256>>>(sc, Pph);

    // head = q + P @ q  (single x single; trans-B; single fp16 out)
    gemm_hh<EP_HEAD, 1, 1, 1><<<dim3(8, 16, 2), 256, GEMM_SMEM>>>(
        Pph, nullptr, qh, ql, nullptr, hdh, nullptr, nullptr,
        SS, DD, sSS, sSD, sSD, sSD, 2);

    // h = head @ Wsum + bias  fp32  (single-A)
    gemm_hh<EP_BIAS, 0, 1, 0><<<dim3(8, 32, 1), 256, GEMM_SMEM>>>(
        hdh, nullptr, wsT, nullptr, hhf, nullptr, nullptr, obias,
        DD, DD, 0, 0, 0, 0, 0);

    // layernorm -> single fp16
    ln_single<<<BSR, 256>>>(hhf, hnh);

    // f = swish(h @ wi)  (single-A; single fp16 out)
    gemm_hh<EP_SWISH, 0, 1, 1><<<dim3(8, 32, 1), 256, GEMM_SMEM>>>(
        hnh, nullptr, wT, nullptr, nullptr, fh, nullptr, nullptr,
        DD, DD, 0, 0, 0, 0, 0);

    // out = f @ wi  fp32  (single-A)
    gemm_hh<EP_OUT, 0, 1, 0><<<dim3(8, 32, 1), 256, GEMM_SMEM>>>(
        fh, nullptr, wT, nullptr, out, nullptr, nullptr, nullptr,
        DD, DD, 0, 0, 0, 0, 0);
}